// round 1
// baseline (speedup 1.0000x reference)
#include <cuda_runtime.h>

// Problem constants
#define SQ   2048                 // sequence length
#define BB   2                    // batch
#define HID  1024                 // hidden
#define NH   16                   // heads
#define DH   64                   // head dim
#define RK   64                   // LoRA rank
#define NT   (SQ*BB)              // 4096 tokens
#define BHN  (BB*NH)              // 32 (b,h) pairs
#define CTXE ((size_t)SQ*BB*HID)  // 4194304 context elements

// Scratch (device globals: no allocation allowed)
__device__ float g_t[3][NT*RK];          // A-stage outputs (q,k,v) [4096,64]
__device__ float g_qkv[3][BHN*SQ*DH];    // projected q,k,v in [b*h, s, d]
__device__ float g_sq[2][BHN*SQ];        // ||q||^2, ||k||^2

typedef unsigned long long u64;

__device__ __forceinline__ u64 pk2(float a, float b){
    u64 r; asm("mov.b64 %0,{%1,%2};" : "=l"(r) : "f"(a), "f"(b)); return r;
}
__device__ __forceinline__ void up2(u64 v, float& a, float& b){
    asm("mov.b64 {%0,%1},%2;" : "=f"(a), "=f"(b) : "l"(v));
}
__device__ __forceinline__ void fma2(u64& d, u64 a, u64 b){
    asm("fma.rn.f32x2 %0,%1,%2,%0;" : "+l"(d) : "l"(a), "l"(b));
}

// ---------------------------------------------------------------------------
// Kernel 1: A-stage  t[4096,64] = x[4096,1024] @ wa[1024,64] + ba
// grid (64 Mtiles, 3 mats), 256 threads, 64x64 tile, 4x4 micro
// ---------------------------------------------------------------------------
__global__ void __launch_bounds__(256) k_proja(
    const float* __restrict__ x,
    const float* __restrict__ w0, const float* __restrict__ b0,
    const float* __restrict__ w1, const float* __restrict__ b1,
    const float* __restrict__ w2, const float* __restrict__ b2)
{
    __shared__ __align__(16) float Xs[64*65];
    __shared__ __align__(16) float Ws[64*64];
    const int mat = blockIdx.y;
    const float* wa = (mat==0) ? w0 : (mat==1 ? w1 : w2);
    const float* ba = (mat==0) ? b0 : (mat==1 ? b1 : b2);
    const int m0 = blockIdx.x * 64;
    const int tid = threadIdx.x, tx = tid & 15, ty = tid >> 4;

    u64 acc[4][2];
#pragma unroll
    for (int i = 0; i < 4; i++){ acc[i][0] = 0ull; acc[i][1] = 0ull; }

    for (int k0 = 0; k0 < HID; k0 += 64){
        __syncthreads();
#pragma unroll
        for (int it = 0; it < 4; it++){
            int e = tid + it*256;
            int r = e >> 4, c = (e & 15)*4;
            float4 v = *reinterpret_cast<const float4*>(x + (size_t)(m0+r)*HID + k0 + c);
            Xs[r*65+c+0]=v.x; Xs[r*65+c+1]=v.y; Xs[r*65+c+2]=v.z; Xs[r*65+c+3]=v.w;
            float4 w = *reinterpret_cast<const float4*>(wa + (size_t)(k0+r)*RK + c);
            *reinterpret_cast<float4*>(&Ws[r*64+c]) = w;
        }
        __syncthreads();
#pragma unroll 8
        for (int k = 0; k < 64; k++){
            ulonglong2 bp = *reinterpret_cast<const ulonglong2*>(&Ws[k*64 + tx*4]);
#pragma unroll
            for (int i = 0; i < 4; i++){
                float a = Xs[(ty*4+i)*65 + k];
                u64 ai = pk2(a, a);
                fma2(acc[i][0], ai, bp.x);
                fma2(acc[i][1], ai, bp.y);
            }
        }
    }
    float* outp = g_t[mat];
    float bi0 = ba[tx*4+0], bi1 = ba[tx*4+1], bi2 = ba[tx*4+2], bi3 = ba[tx*4+3];
#pragma unroll
    for (int i = 0; i < 4; i++){
        float v0,v1,v2,v3; up2(acc[i][0],v0,v1); up2(acc[i][1],v2,v3);
        float4 o = make_float4(v0+bi0, v1+bi1, v2+bi2, v3+bi3);
        *reinterpret_cast<float4*>(outp + (size_t)(m0+ty*4+i)*RK + tx*4) = o;
    }
}

// ---------------------------------------------------------------------------
// Kernel 2: B-stage  q/k/v[4096,1024] = t[4096,64] @ wb[64,1024] + bb
// relayout to [b*h, s, d]; fused ||row||^2 for q,k.
// grid (64 Mtiles, 16 heads, 3 mats), 256 threads.
// ---------------------------------------------------------------------------
__global__ void __launch_bounds__(256) k_projb(
    const float* __restrict__ w0, const float* __restrict__ b0,
    const float* __restrict__ w1, const float* __restrict__ b1,
    const float* __restrict__ w2, const float* __restrict__ b2)
{
    __shared__ __align__(16) float Ts[64*65];
    __shared__ __align__(16) float Ws[64*64];
    const int mat = blockIdx.z;
    const int h   = blockIdx.y;
    const int m0  = blockIdx.x * 64;
    const float* wb = (mat==0) ? w0 : (mat==1 ? w1 : w2);
    const float* bb = (mat==0) ? b0 : (mat==1 ? b1 : b2);
    const float* tin = g_t[mat];
    const int tid = threadIdx.x, tx = tid & 15, ty = tid >> 4;

#pragma unroll
    for (int it = 0; it < 4; it++){
        int e = tid + it*256;
        int r = e >> 4, c = (e & 15)*4;
        float4 v = *reinterpret_cast<const float4*>(tin + (size_t)(m0+r)*RK + c);
        Ts[r*65+c+0]=v.x; Ts[r*65+c+1]=v.y; Ts[r*65+c+2]=v.z; Ts[r*65+c+3]=v.w;
        float4 w = *reinterpret_cast<const float4*>(wb + (size_t)r*HID + h*64 + c);
        *reinterpret_cast<float4*>(&Ws[r*64+c]) = w;
    }
    __syncthreads();

    u64 acc[4][2];
#pragma unroll
    for (int i = 0; i < 4; i++){ acc[i][0]=0ull; acc[i][1]=0ull; }
#pragma unroll 8
    for (int k = 0; k < 64; k++){
        ulonglong2 bp = *reinterpret_cast<const ulonglong2*>(&Ws[k*64 + tx*4]);
#pragma unroll
        for (int i = 0; i < 4; i++){
            float a = Ts[(ty*4+i)*65 + k];
            u64 ai = pk2(a, a);
            fma2(acc[i][0], ai, bp.x);
            fma2(acc[i][1], ai, bp.y);
        }
    }
    float bi0 = bb[h*64+tx*4+0], bi1 = bb[h*64+tx*4+1];
    float bi2 = bb[h*64+tx*4+2], bi3 = bb[h*64+tx*4+3];
    float* qkvp = g_qkv[mat];
#pragma unroll
    for (int i = 0; i < 4; i++){
        int m = m0 + ty*4 + i;
        int s = m >> 1, bq = m & 1;
        int bh = bq*NH + h;
        float v0,v1,v2,v3; up2(acc[i][0],v0,v1); up2(acc[i][1],v2,v3);
        v0 += bi0; v1 += bi1; v2 += bi2; v3 += bi3;
        *reinterpret_cast<float4*>(qkvp + ((size_t)bh*SQ + s)*DH + tx*4)
            = make_float4(v0,v1,v2,v3);
        if (mat < 2){
            float rs = v0*v0 + v1*v1 + v2*v2 + v3*v3;
#pragma unroll
            for (int off = 8; off; off >>= 1)
                rs += __shfl_xor_sync(0xffffffffu, rs, off);
            if (tx == 0) g_sq[mat][(size_t)bh*SQ + s] = rs;
        }
    }
}

// ---------------------------------------------------------------------------
// Kernel 3: fused attention.
// Per CTA: 64 query rows of one (b,h). Loop 32 key tiles of 64:
//   S = (qsq + ksq - 2 QK^T) * (-1/16)  -> STG scores -> P = exp(S) -> ctx += P V
// smem: Qs (swizzled) + KVs (K^T then V) + Ps (swizzled) = 48KB exactly.
// ---------------------------------------------------------------------------
__global__ void __launch_bounds__(256) k_attn(float* __restrict__ out)
{
    __shared__ __align__(16) float Qs[64*64];
    __shared__ __align__(16) float KVs[64*64];
    __shared__ __align__(16) float Ps[64*64];

    const int bh = blockIdx.y;
    const int b  = bh >> 4, h = bh & 15;
    const int s0 = blockIdx.x * 64;
    const int tid = threadIdx.x, tx = tid & 15, ty = tid >> 4;

    const float* qp = g_qkv[0] + ((size_t)bh*SQ + s0)*DH;
    const float* kp = g_qkv[1] + (size_t)bh*SQ*DH;
    const float* vp = g_qkv[2] + (size_t)bh*SQ*DH;
    float* outS = out + CTXE + (size_t)bh*SQ*SQ;

    // load Q tile with XOR swizzle (scalar-granularity, conflict-free a-loads)
#pragma unroll
    for (int it = 0; it < 4; it++){
        int e = tid + it*256;
        int r = e >> 4, c = (e & 15)*4;
        float4 v = *reinterpret_cast<const float4*>(qp + (size_t)r*DH + c);
        int sw = r & 7;
        Qs[r*64 + ((c+0)^sw)] = v.x;
        Qs[r*64 + ((c+1)^sw)] = v.y;
        Qs[r*64 + ((c+2)^sw)] = v.z;
        Qs[r*64 + ((c+3)^sw)] = v.w;
    }
    float qsqv[4];
#pragma unroll
    for (int i = 0; i < 4; i++)
        qsqv[i] = g_sq[0][(size_t)bh*SQ + s0 + ty*4 + i];

    u64 acc2[4][2];
#pragma unroll
    for (int i = 0; i < 4; i++){ acc2[i][0]=0ull; acc2[i][1]=0ull; }

    for (int kt = 0; kt < 32; kt++){
        const int t0 = kt * 64;
        __syncthreads();  // previous iter done with KVs/Ps
        // load K tile transposed: KVs[d][t]
#pragma unroll
        for (int it = 0; it < 4; it++){
            int e = tid + it*256;
            int t = e >> 4, c = (e & 15)*4;
            float4 v = *reinterpret_cast<const float4*>(kp + (size_t)(t0+t)*DH + c);
            KVs[(c+0)*64 + t] = v.x;
            KVs[(c+1)*64 + t] = v.y;
            KVs[(c+2)*64 + t] = v.z;
            KVs[(c+3)*64 + t] = v.w;
        }
        float ksqv[4];
#pragma unroll
        for (int j = 0; j < 4; j++)
            ksqv[j] = g_sq[1][(size_t)bh*SQ + t0 + tx*4 + j];
        __syncthreads();

        // GEMM1: qk[s][t]
        u64 acc1[4][2];
#pragma unroll
        for (int i = 0; i < 4; i++){ acc1[i][0]=0ull; acc1[i][1]=0ull; }
#pragma unroll 8
        for (int d = 0; d < 64; d++){
            ulonglong2 bp = *reinterpret_cast<const ulonglong2*>(&KVs[d*64 + tx*4]);
#pragma unroll
            for (int i = 0; i < 4; i++){
                int row = ty*4 + i;
                float a = Qs[row*64 + (d ^ (row & 7))];
                u64 ai = pk2(a, a);
                fma2(acc1[i][0], ai, bp.x);
                fma2(acc1[i][1], ai, bp.y);
            }
        }

        // epilogue: scores -> gmem, probs -> registers
        float pb[4][4];
#pragma unroll
        for (int i = 0; i < 4; i++){
            float d0,d1,d2,d3;
            up2(acc1[i][0], d0, d1); up2(acc1[i][1], d2, d3);
            float qs = qsqv[i];
            float sc0 = (qs + ksqv[0] - 2.0f*d0) * -0.0625f;
            float sc1 = (qs + ksqv[1] - 2.0f*d1) * -0.0625f;
            float sc2 = (qs + ksqv[2] - 2.0f*d2) * -0.0625f;
            float sc3 = (qs + ksqv[3] - 2.0f*d3) * -0.0625f;
            *reinterpret_cast<float4*>(outS + (size_t)(s0+ty*4+i)*SQ + t0 + tx*4)
                = make_float4(sc0, sc1, sc2, sc3);
            pb[i][0] = __expf(sc0); pb[i][1] = __expf(sc1);
            pb[i][2] = __expf(sc2); pb[i][3] = __expf(sc3);
        }

        __syncthreads();  // everyone done reading K^T
        // write P (swizzled), load V into KVs (natural layout)
#pragma unroll
        for (int i = 0; i < 4; i++){
            int row = ty*4 + i;
            int sw = row & 7;
#pragma unroll
            for (int j = 0; j < 4; j++)
                Ps[row*64 + ((tx*4+j) ^ sw)] = pb[i][j];
        }
#pragma unroll
        for (int it = 0; it < 4; it++){
            int e = tid + it*256;
            int t = e >> 4, c = (e & 15)*4;
            float4 v = *reinterpret_cast<const float4*>(vp + (size_t)(t0+t)*DH + c);
            *reinterpret_cast<float4*>(&KVs[t*64 + c]) = v;
        }
        __syncthreads();

        // GEMM2: ctx += P @ V
#pragma unroll 8
        for (int t = 0; t < 64; t++){
            ulonglong2 bp = *reinterpret_cast<const ulonglong2*>(&KVs[t*64 + tx*4]);
#pragma unroll
            for (int i = 0; i < 4; i++){
                int row = ty*4 + i;
                float a = Ps[row*64 + (t ^ (row & 7))];
                u64 ai = pk2(a, a);
                fma2(acc2[i][0], ai, bp.x);
                fma2(acc2[i][1], ai, bp.y);
            }
        }
    }

    // context out: [s, b, h*64+d]
#pragma unroll
    for (int i = 0; i < 4; i++){
        float v0,v1,v2,v3; up2(acc2[i][0],v0,v1); up2(acc2[i][1],v2,v3);
        int s = s0 + ty*4 + i;
        *reinterpret_cast<float4*>(out + (size_t)s*(BB*HID) + b*HID + h*64 + tx*4)
            = make_float4(v0,v1,v2,v3);
    }
}

// ---------------------------------------------------------------------------
extern "C" void kernel_launch(void* const* d_in, const int* in_sizes, int n_in,
                              void* d_out, int out_size)
{
    const float* x   = (const float*)d_in[0];
    const float* wqa = (const float*)d_in[1];
    const float* bqa = (const float*)d_in[2];
    const float* wqb = (const float*)d_in[3];
    const float* bqb = (const float*)d_in[4];
    const float* wka = (const float*)d_in[5];
    const float* bka = (const float*)d_in[6];
    const float* wkb = (const float*)d_in[7];
    const float* bkb = (const float*)d_in[8];
    const float* wva = (const float*)d_in[9];
    const float* bva = (const float*)d_in[10];
    const float* wvb = (const float*)d_in[11];
    const float* bvb = (const float*)d_in[12];
    float* out = (float*)d_out;

    k_proja<<<dim3(64, 3), 256>>>(x, wqa, bqa, wka, bka, wva, bva);
    k_projb<<<dim3(64, 16, 3), 256>>>(wqb, bqb, wkb, bkb, wvb, bvb);
    k_attn<<<dim3(32, 32), 256>>>(out);
}

// round 6
// speedup vs baseline: 2.5401x; 2.5401x over previous
#include <cuda_runtime.h>
#include <cuda_bf16.h>
#include <cstdint>

#define SQ   2048
#define BB   2
#define HID  1024
#define NH   16
#define DH   64
#define RK   64
#define NT   (SQ*BB)
#define BHN  (BB*NH)
#define CTXE ((size_t)SQ*BB*HID)

// ---------------- device scratch (no allocation allowed) ----------------
__device__ float g_t[3][NT*RK];            // A-stage outputs
__device__ float g_sq[2][BHN*SQ];          // ||q||^2, ||k||^2 (fp32 exact)
__device__ __nv_bfloat16 g_qhi[BHN*SQ*DH], g_qlo[BHN*SQ*DH];
__device__ __nv_bfloat16 g_khi[BHN*SQ*DH], g_klo[BHN*SQ*DH];
__device__ __nv_bfloat16 g_vhi[BHN*SQ*DH], g_vlo[BHN*SQ*DH];

typedef unsigned long long u64;

__device__ __forceinline__ u64 pk2(float a, float b){
    u64 r; asm("mov.b64 %0,{%1,%2};" : "=l"(r) : "f"(a), "f"(b)); return r;
}
__device__ __forceinline__ void up2(u64 v, float& a, float& b){
    asm("mov.b64 {%0,%1},%2;" : "=f"(a), "=f"(b) : "l"(v));
}
__device__ __forceinline__ void fma2(u64& d, u64 a, u64 b){
    asm("fma.rn.f32x2 %0,%1,%2,%0;" : "+l"(d) : "l"(a), "l"(b));
}
__device__ __forceinline__ uint32_t s2u(const void* p){
    uint32_t a;
    asm("{ .reg .u64 t; cvta.to.shared.u64 t, %1; cvt.u32.u64 %0, t; }" : "=r"(a) : "l"(p));
    return a;
}

// ---------------- mma.sync helpers (baseline ISA, no 'a' features) ------
__device__ __forceinline__ void ldmx4(uint32_t& r0, uint32_t& r1, uint32_t& r2, uint32_t& r3,
                                      uint32_t addr){
    asm volatile("ldmatrix.sync.aligned.m8n8.x4.shared.b16 {%0,%1,%2,%3}, [%4];"
        : "=r"(r0), "=r"(r1), "=r"(r2), "=r"(r3) : "r"(addr));
}
__device__ __forceinline__ void ldmx4t(uint32_t& r0, uint32_t& r1, uint32_t& r2, uint32_t& r3,
                                       uint32_t addr){
    asm volatile("ldmatrix.sync.aligned.m8n8.x4.trans.shared.b16 {%0,%1,%2,%3}, [%4];"
        : "=r"(r0), "=r"(r1), "=r"(r2), "=r"(r3) : "r"(addr));
}
__device__ __forceinline__ void mma16816(float* d, const uint32_t* a, uint32_t b0, uint32_t b1){
    asm volatile("mma.sync.aligned.m16n8k16.row.col.f32.bf16.bf16.f32 "
        "{%0,%1,%2,%3},{%4,%5,%6,%7},{%8,%9},{%0,%1,%2,%3};"
        : "+f"(d[0]), "+f"(d[1]), "+f"(d[2]), "+f"(d[3])
        : "r"(a[0]), "r"(a[1]), "r"(a[2]), "r"(a[3]), "r"(b0), "r"(b1));
}
__device__ __forceinline__ void split2(float x, float y, uint32_t& hi, uint32_t& lo){
    __nv_bfloat16 hx = __float2bfloat16_rn(x), hy = __float2bfloat16_rn(y);
    __nv_bfloat16 lx = __float2bfloat16_rn(x - __bfloat162float(hx));
    __nv_bfloat16 ly = __float2bfloat16_rn(y - __bfloat162float(hy));
    __nv_bfloat162 hp; hp.x = hx; hp.y = hy;
    __nv_bfloat162 lp; lp.x = lx; lp.y = ly;
    hi = *reinterpret_cast<uint32_t*>(&hp);
    lo = *reinterpret_cast<uint32_t*>(&lp);
}

// ---------------------------------------------------------------------------
// Kernel 1: A-stage  t[4096,64] = x @ wa + ba.  32-row tiles, grid (128,3).
// ---------------------------------------------------------------------------
__global__ void __launch_bounds__(256) k_proja(
    const float* __restrict__ x,
    const float* __restrict__ w0, const float* __restrict__ b0,
    const float* __restrict__ w1, const float* __restrict__ b1,
    const float* __restrict__ w2, const float* __restrict__ b2)
{
    __shared__ float Xs[32*65];
    __shared__ __align__(16) float Ws[64*64];
    const int mat = blockIdx.y;
    const float* wa = (mat==0) ? w0 : (mat==1 ? w1 : w2);
    const float* ba = (mat==0) ? b0 : (mat==1 ? b1 : b2);
    const int m0 = blockIdx.x * 32;
    const int tid = threadIdx.x, tx = tid & 15, ty = tid >> 4;

    u64 acc[2][2];
#pragma unroll
    for (int i = 0; i < 2; i++){ acc[i][0]=0ull; acc[i][1]=0ull; }

    for (int k0 = 0; k0 < HID; k0 += 64){
        __syncthreads();
#pragma unroll
        for (int it = 0; it < 2; it++){
            int e = tid + it*256;
            int r = e >> 4, c = (e & 15)*4;
            float4 v = *reinterpret_cast<const float4*>(x + (size_t)(m0+r)*HID + k0 + c);
            Xs[r*65+c+0]=v.x; Xs[r*65+c+1]=v.y; Xs[r*65+c+2]=v.z; Xs[r*65+c+3]=v.w;
        }
#pragma unroll
        for (int it = 0; it < 4; it++){
            int e = tid + it*256;
            int r = e >> 4, c = (e & 15)*4;
            *reinterpret_cast<float4*>(&Ws[r*64+c]) =
                *reinterpret_cast<const float4*>(wa + (size_t)(k0+r)*RK + c);
        }
        __syncthreads();
#pragma unroll 8
        for (int k = 0; k < 64; k++){
            ulonglong2 bp = *reinterpret_cast<const ulonglong2*>(&Ws[k*64 + tx*4]);
#pragma unroll
            for (int i = 0; i < 2; i++){
                float a = Xs[(ty*2+i)*65 + k];
                u64 ai = pk2(a, a);
                fma2(acc[i][0], ai, bp.x);
                fma2(acc[i][1], ai, bp.y);
            }
        }
    }
    float* outp = g_t[mat];
    float bi0 = ba[tx*4+0], bi1 = ba[tx*4+1], bi2 = ba[tx*4+2], bi3 = ba[tx*4+3];
#pragma unroll
    for (int i = 0; i < 2; i++){
        float v0,v1,v2,v3; up2(acc[i][0],v0,v1); up2(acc[i][1],v2,v3);
        *reinterpret_cast<float4*>(outp + (size_t)(m0+ty*2+i)*RK + tx*4)
            = make_float4(v0+bi0, v1+bi1, v2+bi2, v3+bi3);
    }
}

// ---------------------------------------------------------------------------
// Kernel 2: B-stage + bf16 hi/lo split emit + ||row||^2.  All of q,k,v stored
// [bh, s, d] (coalesced).  grid (64 Mtiles, 16 heads, 3 mats), 256 threads.
// ---------------------------------------------------------------------------
__global__ void __launch_bounds__(256) k_projb(
    const float* __restrict__ w0, const float* __restrict__ b0,
    const float* __restrict__ w1, const float* __restrict__ b1,
    const float* __restrict__ w2, const float* __restrict__ b2)
{
    __shared__ float Ts[64*65];
    __shared__ __align__(16) float Ws[64*64];
    const int mat = blockIdx.z;
    const int h   = blockIdx.y;
    const int m0  = blockIdx.x * 64;
    const float* wb = (mat==0) ? w0 : (mat==1 ? w1 : w2);
    const float* bb = (mat==0) ? b0 : (mat==1 ? b1 : b2);
    const float* tin = g_t[mat];
    const int tid = threadIdx.x, tx = tid & 15, ty = tid >> 4;

#pragma unroll
    for (int it = 0; it < 4; it++){
        int e = tid + it*256;
        int r = e >> 4, c = (e & 15)*4;
        float4 v = *reinterpret_cast<const float4*>(tin + (size_t)(m0+r)*RK + c);
        Ts[r*65+c+0]=v.x; Ts[r*65+c+1]=v.y; Ts[r*65+c+2]=v.z; Ts[r*65+c+3]=v.w;
        *reinterpret_cast<float4*>(&Ws[r*64+c]) =
            *reinterpret_cast<const float4*>(wb + (size_t)r*HID + h*64 + c);
    }
    __syncthreads();

    u64 acc[4][2];
#pragma unroll
    for (int i = 0; i < 4; i++){ acc[i][0]=0ull; acc[i][1]=0ull; }
#pragma unroll 8
    for (int k = 0; k < 64; k++){
        ulonglong2 bp = *reinterpret_cast<const ulonglong2*>(&Ws[k*64 + tx*4]);
#pragma unroll
        for (int i = 0; i < 4; i++){
            float a = Ts[(ty*4+i)*65 + k];
            u64 ai = pk2(a, a);
            fma2(acc[i][0], ai, bp.x);
            fma2(acc[i][1], ai, bp.y);
        }
    }
    float bi0 = bb[h*64+tx*4+0], bi1 = bb[h*64+tx*4+1];
    float bi2 = bb[h*64+tx*4+2], bi3 = bb[h*64+tx*4+3];
#pragma unroll
    for (int i = 0; i < 4; i++){
        int m = m0 + ty*4 + i;
        int s = m >> 1, bq = m & 1;
        int bh = bq*NH + h;
        float v0,v1,v2,v3; up2(acc[i][0],v0,v1); up2(acc[i][1],v2,v3);
        v0 += bi0; v1 += bi1; v2 += bi2; v3 += bi3;

        __nv_bfloat16 h0 = __float2bfloat16_rn(v0);
        __nv_bfloat16 h1 = __float2bfloat16_rn(v1);
        __nv_bfloat16 h2 = __float2bfloat16_rn(v2);
        __nv_bfloat16 h3 = __float2bfloat16_rn(v3);
        __nv_bfloat16 l0 = __float2bfloat16_rn(v0 - __bfloat162float(h0));
        __nv_bfloat16 l1 = __float2bfloat16_rn(v1 - __bfloat162float(h1));
        __nv_bfloat16 l2 = __float2bfloat16_rn(v2 - __bfloat162float(h2));
        __nv_bfloat16 l3 = __float2bfloat16_rn(v3 - __bfloat162float(h3));

        __nv_bfloat16* ph = (mat==0) ? g_qhi : (mat==1 ? g_khi : g_vhi);
        __nv_bfloat16* pl = (mat==0) ? g_qlo : (mat==1 ? g_klo : g_vlo);
        size_t base = ((size_t)bh*SQ + s)*DH + tx*4;
        ph[base+0]=h0; ph[base+1]=h1; ph[base+2]=h2; ph[base+3]=h3;
        pl[base+0]=l0; pl[base+1]=l1; pl[base+2]=l2; pl[base+3]=l3;

        if (mat < 2){
            float rs = v0*v0 + v1*v1 + v2*v2 + v3*v3;
#pragma unroll
            for (int off = 8; off; off >>= 1)
                rs += __shfl_xor_sync(0xffffffffu, rs, off);
            if (tx == 0) g_sq[mat][(size_t)bh*SQ + s] = rs;
        }
    }
}

// ---------------------------------------------------------------------------
// Kernel 3: mma.sync bf16x3 attention.  CTA = 128 q-rows, 16 key tiles of 128.
// ---------------------------------------------------------------------------
#define QK_ST 72     // bf16 row stride for Q/K/V tiles (4 words mod 32: no conflicts)
#define P_ST  136    // bf16 row stride for P tiles
#define SM_QSQ 0
#define SM_KSQ 512
#define SM_QHI 1024
#define SM_QLO (SM_QHI + 18432)
#define SM_KHI (SM_QLO + 18432)
#define SM_KLO (SM_KHI + 18432)
#define SM_VHI (SM_KLO + 18432)
#define SM_VLO (SM_VHI + 18432)
#define SM_PHI (SM_VLO + 18432)
#define SM_PLO (SM_PHI + 34816)
#define SM_TOTAL (SM_PLO + 34816)   // 181248 bytes

__global__ void __launch_bounds__(256) k_attn(float* __restrict__ out)
{
    extern __shared__ __align__(16) char sm[];
    const uint32_t sb = s2u(sm);
    const int tid = threadIdx.x, lid = tid & 31, wid = tid >> 5;
    const int bh = blockIdx.y, b = bh >> 4, h = bh & 15;
    const int s0 = blockIdx.x * 128;

    // ---- resident Q tiles (hi/lo) + qsq ----
    {
        const __nv_bfloat16* qh = g_qhi + ((size_t)bh*SQ + s0)*DH;
        const __nv_bfloat16* ql = g_qlo + ((size_t)bh*SQ + s0)*DH;
#pragma unroll
        for (int it = 0; it < 4; it++){
            int e = tid + it*256;             // 1024 x 16B chunks
            int r = e >> 3, c8 = (e & 7)*8;
            uint32_t so = (uint32_t)(r*QK_ST + c8)*2u;
            *reinterpret_cast<uint4*>(sm + SM_QHI + so) =
                *reinterpret_cast<const uint4*>(qh + (size_t)r*DH + c8);
            *reinterpret_cast<uint4*>(sm + SM_QLO + so) =
                *reinterpret_cast<const uint4*>(ql + (size_t)r*DH + c8);
        }
        if (tid < 128)
            reinterpret_cast<float*>(sm + SM_QSQ)[tid] = g_sq[0][(size_t)bh*SQ + s0 + tid];
    }

    const int m0 = (wid & 3) * 32;   // warp M base (both GEMMs)
    const int n1 = (wid >> 2) * 64;  // GEMM1 N base (key cols)
    const int n2 = (wid >> 2) * 32;  // GEMM2 N base (head-dim cols)

    float acc2[2][4][4];
#pragma unroll
    for (int mt = 0; mt < 2; mt++)
#pragma unroll
        for (int nt = 0; nt < 4; nt++)
#pragma unroll
            for (int q = 0; q < 4; q++) acc2[mt][nt][q] = 0.0f;

    for (int kt = 0; kt < 16; kt++){
        __syncthreads();   // prev GEMM2 done reading P/V; K/V free
        // ---- load K, V (hi/lo) + ksq ----
        {
            const size_t off = ((size_t)bh*SQ + kt*128)*DH;
#pragma unroll
            for (int it = 0; it < 4; it++){
                int e = tid + it*256;
                int r = e >> 3, c8 = (e & 7)*8;
                uint32_t so = (uint32_t)(r*QK_ST + c8)*2u;
                size_t go = off + (size_t)r*DH + c8;
                *reinterpret_cast<uint4*>(sm + SM_KHI + so) = *reinterpret_cast<const uint4*>(g_khi + go);
                *reinterpret_cast<uint4*>(sm + SM_KLO + so) = *reinterpret_cast<const uint4*>(g_klo + go);
                *reinterpret_cast<uint4*>(sm + SM_VHI + so) = *reinterpret_cast<const uint4*>(g_vhi + go);
                *reinterpret_cast<uint4*>(sm + SM_VLO + so) = *reinterpret_cast<const uint4*>(g_vlo + go);
            }
            if (tid < 128)
                reinterpret_cast<float*>(sm + SM_KSQ)[tid] = g_sq[1][(size_t)bh*SQ + kt*128 + tid];
        }
        __syncthreads();

        // ---- GEMM1: qk = Q.K^T  (bf16 x3 passes) ----
        float acc1[2][8][4];
#pragma unroll
        for (int mt = 0; mt < 2; mt++)
#pragma unroll
            for (int nt = 0; nt < 8; nt++)
#pragma unroll
                for (int q = 0; q < 4; q++) acc1[mt][nt][q] = 0.0f;

#pragma unroll
        for (int p = 0; p < 3; p++){
            const uint32_t Ab = sb + ((p == 2) ? SM_QLO : SM_QHI);
            const uint32_t Bb = sb + ((p == 1) ? SM_KLO : SM_KHI);
#pragma unroll
            for (int ks = 0; ks < 4; ks++){
                const int d0 = ks*16;
                uint32_t a[2][4];
#pragma unroll
                for (int mt = 0; mt < 2; mt++){
                    int row = m0 + mt*16 + (lid & 15);
                    int col = d0 + ((lid >> 4) << 3);
                    ldmx4(a[mt][0], a[mt][1], a[mt][2], a[mt][3],
                          Ab + (uint32_t)(row*QK_ST + col)*2u);
                }
#pragma unroll
                for (int ntp = 0; ntp < 4; ntp++){
                    int row = n1 + ntp*16 + (lid & 7) + ((lid >> 4) << 3);
                    int col = d0 + (((lid >> 3) & 1) << 3);
                    uint32_t r0, r1, r2, r3;
                    ldmx4(r0, r1, r2, r3, Bb + (uint32_t)(row*QK_ST + col)*2u);
#pragma unroll
                    for (int mt = 0; mt < 2; mt++){
                        mma16816(acc1[mt][2*ntp],   a[mt], r0, r1);
                        mma16816(acc1[mt][2*ntp+1], a[mt], r2, r3);
                    }
                }
            }
        }

        // ---- epilogue: scores -> gmem, P = exp(score) split hi/lo -> smem ----
        {
            const float* qsq = reinterpret_cast<const float*>(sm + SM_QSQ);
            const float* ksq = reinterpret_cast<const float*>(sm + SM_KSQ);
#pragma unroll
            for (int mt = 0; mt < 2; mt++){
                int rlo = m0 + mt*16 + (lid >> 2);
                float q0 = qsq[rlo], q1 = qsq[rlo + 8];
                float* sr0 = out + CTXE + ((size_t)bh*SQ + (size_t)(s0 + rlo))*SQ + kt*128;
                float* sr1 = sr0 + (size_t)8*SQ;
#pragma unroll
                for (int nt = 0; nt < 8; nt++){
                    int col = n1 + nt*8 + 2*(lid & 3);
                    float k0 = ksq[col], k1 = ksq[col+1];
                    float s00 = fmaf(0.125f, acc1[mt][nt][0], -0.0625f*(q0 + k0));
                    float s01 = fmaf(0.125f, acc1[mt][nt][1], -0.0625f*(q0 + k1));
                    float s10 = fmaf(0.125f, acc1[mt][nt][2], -0.0625f*(q1 + k0));
                    float s11 = fmaf(0.125f, acc1[mt][nt][3], -0.0625f*(q1 + k1));
                    *reinterpret_cast<float2*>(sr0 + col) = make_float2(s00, s01);
                    *reinterpret_cast<float2*>(sr1 + col) = make_float2(s10, s11);
                    uint32_t hw, lw;
                    split2(__expf(s00), __expf(s01), hw, lw);
                    *reinterpret_cast<uint32_t*>(sm + SM_PHI + (uint32_t)(rlo*P_ST + col)*2u) = hw;
                    *reinterpret_cast<uint32_t*>(sm + SM_PLO + (uint32_t)(rlo*P_ST + col)*2u) = lw;
                    split2(__expf(s10), __expf(s11), hw, lw);
                    *reinterpret_cast<uint32_t*>(sm + SM_PHI + (uint32_t)((rlo+8)*P_ST + col)*2u) = hw;
                    *reinterpret_cast<uint32_t*>(sm + SM_PLO + (uint32_t)((rlo+8)*P_ST + col)*2u) = lw;
                }
            }
        }
        __syncthreads();

        // ---- GEMM2: ctx += P.V  (bf16 x3 passes; V via ldmatrix.trans) ----
#pragma unroll
        for (int p = 0; p < 3; p++){
            const uint32_t Ab = sb + ((p == 2) ? SM_PLO : SM_PHI);
            const uint32_t Bb = sb + ((p == 1) ? SM_VLO : SM_VHI);
#pragma unroll
            for (int ks = 0; ks < 8; ks++){
                const int t0 = ks*16;
                uint32_t a[2][4];
#pragma unroll
                for (int mt = 0; mt < 2; mt++){
                    int row = m0 + mt*16 + (lid & 15);
                    int col = t0 + ((lid >> 4) << 3);
                    ldmx4(a[mt][0], a[mt][1], a[mt][2], a[mt][3],
                          Ab + (uint32_t)(row*P_ST + col)*2u);
                }
#pragma unroll
                for (int dtp = 0; dtp < 2; dtp++){
                    int row = t0 + (lid & 7) + (((lid >> 3) & 1) << 3);
                    int col = n2 + dtp*16 + ((lid >> 4) << 3);
                    uint32_t r0, r1, r2, r3;
                    ldmx4t(r0, r1, r2, r3, Bb + (uint32_t)(row*QK_ST + col)*2u);
#pragma unroll
                    for (int mt = 0; mt < 2; mt++){
                        mma16816(acc2[mt][2*dtp],   a[mt], r0, r1);
                        mma16816(acc2[mt][2*dtp+1], a[mt], r2, r3);
                    }
                }
            }
        }
    }

    // ---- context epilogue: [s, b, h*64+d] ----
#pragma unroll
    for (int mt = 0; mt < 2; mt++){
        int rlo = m0 + mt*16 + (lid >> 2);
        float* o0 = out + (size_t)(s0 + rlo)*(BB*HID) + (size_t)b*HID + h*DH;
        float* o1 = o0 + (size_t)8*(BB*HID);
#pragma unroll
        for (int nt = 0; nt < 4; nt++){
            int col = n2 + nt*8 + 2*(lid & 3);
            *reinterpret_cast<float2*>(o0 + col) = make_float2(acc2[mt][nt][0], acc2[mt][nt][1]);
            *reinterpret_cast<float2*>(o1 + col) = make_float2(acc2[mt][nt][2], acc2[mt][nt][3]);
        }
    }
}

// ---------------------------------------------------------------------------
extern "C" void kernel_launch(void* const* d_in, const int* in_sizes, int n_in,
                              void* d_out, int out_size)
{
    const float* x   = (const float*)d_in[0];
    const float* wqa = (const float*)d_in[1];
    const float* bqa = (const float*)d_in[2];
    const float* wqb = (const float*)d_in[3];
    const float* bqb = (const float*)d_in[4];
    const float* wka = (const float*)d_in[5];
    const float* bka = (const float*)d_in[6];
    const float* wkb = (const float*)d_in[7];
    const float* bkb = (const float*)d_in[8];
    const float* wva = (const float*)d_in[9];
    const float* bva = (const float*)d_in[10];
    const float* wvb = (const float*)d_in[11];
    const float* bvb = (const float*)d_in[12];
    float* out = (float*)d_out;

    cudaFuncSetAttribute(k_attn, cudaFuncAttributeMaxDynamicSharedMemorySize, SM_TOTAL);

    k_proja<<<dim3(128, 3), 256>>>(x, wqa, bqa, wka, bka, wva, bva);
    k_projb<<<dim3(64, 16, 3), 256>>>(wqb, bqb, wkb, bkb, wvb, bvb);
    k_attn<<<dim3(16, 32), 256, SM_TOTAL>>>(out);
}

// round 8
// speedup vs baseline: 2.9191x; 1.1492x over previous
#include <cuda_runtime.h>
#include <cuda_bf16.h>
#include <cstdint>

#define SQ   2048
#define BB   2
#define HID  1024
#define NH   16
#define DH   64
#define RK   64
#define NT   (SQ*BB)
#define BHN  (BB*NH)
#define CTXE ((size_t)SQ*BB*HID)

// ---------------- device scratch (no allocation allowed) ----------------
__device__ float g_tp[3][4][NT*RK];        // A-stage K-split partials
__device__ float g_sq[2][BHN*SQ];          // ||q||^2, ||k||^2 (fp32 exact)
__device__ __nv_bfloat16 g_qhi[BHN*SQ*DH], g_qlo[BHN*SQ*DH];
__device__ __nv_bfloat16 g_khi[BHN*SQ*DH], g_klo[BHN*SQ*DH];
__device__ __nv_bfloat16 g_vhi[BHN*SQ*DH], g_vlo[BHN*SQ*DH];

typedef unsigned long long u64;

__device__ __forceinline__ u64 pk2(float a, float b){
    u64 r; asm("mov.b64 %0,{%1,%2};" : "=l"(r) : "f"(a), "f"(b)); return r;
}
__device__ __forceinline__ void up2(u64 v, float& a, float& b){
    asm("mov.b64 {%0,%1},%2;" : "=f"(a), "=f"(b) : "l"(v));
}
__device__ __forceinline__ void fma2(u64& d, u64 a, u64 b){
    asm("fma.rn.f32x2 %0,%1,%2,%0;" : "+l"(d) : "l"(a), "l"(b));
}
__device__ __forceinline__ uint32_t s2u(const void* p){
    uint32_t a;
    asm("{ .reg .u64 t; cvta.to.shared.u64 t, %1; cvt.u32.u64 %0, t; }" : "=r"(a) : "l"(p));
    return a;
}

// ---------------- mma.sync helpers (baseline ISA) ------
__device__ __forceinline__ void ldmx4(uint32_t& r0, uint32_t& r1, uint32_t& r2, uint32_t& r3,
                                      uint32_t addr){
    asm volatile("ldmatrix.sync.aligned.m8n8.x4.shared.b16 {%0,%1,%2,%3}, [%4];"
        : "=r"(r0), "=r"(r1), "=r"(r2), "=r"(r3) : "r"(addr));
}
__device__ __forceinline__ void ldmx4t(uint32_t& r0, uint32_t& r1, uint32_t& r2, uint32_t& r3,
                                       uint32_t addr){
    asm volatile("ldmatrix.sync.aligned.m8n8.x4.trans.shared.b16 {%0,%1,%2,%3}, [%4];"
        : "=r"(r0), "=r"(r1), "=r"(r2), "=r"(r3) : "r"(addr));
}
__device__ __forceinline__ void mma16816(float* d, const uint32_t* a, uint32_t b0, uint32_t b1){
    asm volatile("mma.sync.aligned.m16n8k16.row.col.f32.bf16.bf16.f32 "
        "{%0,%1,%2,%3},{%4,%5,%6,%7},{%8,%9},{%0,%1,%2,%3};"
        : "+f"(d[0]), "+f"(d[1]), "+f"(d[2]), "+f"(d[3])
        : "r"(a[0]), "r"(a[1]), "r"(a[2]), "r"(a[3]), "r"(b0), "r"(b1));
}
__device__ __forceinline__ void split2(float x, float y, uint32_t& hi, uint32_t& lo){
    __nv_bfloat16 hx = __float2bfloat16_rn(x), hy = __float2bfloat16_rn(y);
    __nv_bfloat16 lx = __float2bfloat16_rn(x - __bfloat162float(hx));
    __nv_bfloat16 ly = __float2bfloat16_rn(y - __bfloat162float(hy));
    __nv_bfloat162 hp; hp.x = hx; hp.y = hy;
    __nv_bfloat162 lp; lp.x = lx; lp.y = ly;
    hi = *reinterpret_cast<uint32_t*>(&hp);
    lo = *reinterpret_cast<uint32_t*>(&lp);
}

// ---------------------------------------------------------------------------
// Kernel 1: A-stage partial  t_kc = x[:, kc*256:(kc+1)*256] @ wa[kc...] (+ba at kc0)
// grid (64 Mtiles, 3 mats, 4 kchunks), 256 threads, 64x64 tile, 4x4 micro.
// ---------------------------------------------------------------------------
__global__ void __launch_bounds__(256) k_proja(
    const float* __restrict__ x,
    const float* __restrict__ w0, const float* __restrict__ b0,
    const float* __restrict__ w1, const float* __restrict__ b1,
    const float* __restrict__ w2, const float* __restrict__ b2)
{
    __shared__ float Xs[64*65];
    __shared__ __align__(16) float Ws[64*64];
    const int mat = blockIdx.y;
    const int kc  = blockIdx.z;
    const float* wa = (mat==0) ? w0 : (mat==1 ? w1 : w2);
    const float* ba = (mat==0) ? b0 : (mat==1 ? b1 : b2);
    const int m0 = blockIdx.x * 64;
    const int tid = threadIdx.x, tx = tid & 15, ty = tid >> 4;

    u64 acc[4][2];
#pragma unroll
    for (int i = 0; i < 4; i++){ acc[i][0] = 0ull; acc[i][1] = 0ull; }

    for (int k0 = kc*256; k0 < kc*256 + 256; k0 += 64){
        __syncthreads();
#pragma unroll
        for (int it = 0; it < 4; it++){
            int e = tid + it*256;
            int r = e >> 4, c = (e & 15)*4;
            float4 v = *reinterpret_cast<const float4*>(x + (size_t)(m0+r)*HID + k0 + c);
            Xs[r*65+c+0]=v.x; Xs[r*65+c+1]=v.y; Xs[r*65+c+2]=v.z; Xs[r*65+c+3]=v.w;
            *reinterpret_cast<float4*>(&Ws[r*64+c]) =
                *reinterpret_cast<const float4*>(wa + (size_t)(k0+r)*RK + c);
        }
        __syncthreads();
#pragma unroll 8
        for (int k = 0; k < 64; k++){
            ulonglong2 bp = *reinterpret_cast<const ulonglong2*>(&Ws[k*64 + tx*4]);
#pragma unroll
            for (int i = 0; i < 4; i++){
                float a = Xs[(ty*4+i)*65 + k];
                u64 ai = pk2(a, a);
                fma2(acc[i][0], ai, bp.x);
                fma2(acc[i][1], ai, bp.y);
            }
        }
    }
    float* outp = g_tp[mat][kc];
    float bi0 = 0.f, bi1 = 0.f, bi2 = 0.f, bi3 = 0.f;
    if (kc == 0){ bi0 = ba[tx*4+0]; bi1 = ba[tx*4+1]; bi2 = ba[tx*4+2]; bi3 = ba[tx*4+3]; }
#pragma unroll
    for (int i = 0; i < 4; i++){
        float v0,v1,v2,v3; up2(acc[i][0],v0,v1); up2(acc[i][1],v2,v3);
        *reinterpret_cast<float4*>(outp + (size_t)(m0+ty*4+i)*RK + tx*4)
            = make_float4(v0+bi0, v1+bi1, v2+bi2, v3+bi3);
    }
}

// ---------------------------------------------------------------------------
// Kernel 2: B-stage + bf16 hi/lo split emit + ||row||^2.
// Sums the 4 A-stage partials on load.  grid (64, 16, 3), 256 threads.
// ---------------------------------------------------------------------------
__global__ void __launch_bounds__(256) k_projb(
    const float* __restrict__ w0, const float* __restrict__ b0,
    const float* __restrict__ w1, const float* __restrict__ b1,
    const float* __restrict__ w2, const float* __restrict__ b2)
{
    __shared__ float Ts[64*65];
    __shared__ __align__(16) float Ws[64*64];
    const int mat = blockIdx.z;
    const int h   = blockIdx.y;
    const int m0  = blockIdx.x * 64;
    const float* wb = (mat==0) ? w0 : (mat==1 ? w1 : w2);
    const float* bb = (mat==0) ? b0 : (mat==1 ? b1 : b2);
    const int tid = threadIdx.x, tx = tid & 15, ty = tid >> 4;

#pragma unroll
    for (int it = 0; it < 4; it++){
        int e = tid + it*256;
        int r = e >> 4, c = (e & 15)*4;
        size_t off = (size_t)(m0+r)*RK + c;
        float4 v0 = *reinterpret_cast<const float4*>(g_tp[mat][0] + off);
        float4 v1 = *reinterpret_cast<const float4*>(g_tp[mat][1] + off);
        float4 v2 = *reinterpret_cast<const float4*>(g_tp[mat][2] + off);
        float4 v3 = *reinterpret_cast<const float4*>(g_tp[mat][3] + off);
        Ts[r*65+c+0] = v0.x + v1.x + v2.x + v3.x;
        Ts[r*65+c+1] = v0.y + v1.y + v2.y + v3.y;
        Ts[r*65+c+2] = v0.z + v1.z + v2.z + v3.z;
        Ts[r*65+c+3] = v0.w + v1.w + v2.w + v3.w;
        *reinterpret_cast<float4*>(&Ws[r*64+c]) =
            *reinterpret_cast<const float4*>(wb + (size_t)r*HID + h*64 + c);
    }
    __syncthreads();

    u64 acc[4][2];
#pragma unroll
    for (int i = 0; i < 4; i++){ acc[i][0]=0ull; acc[i][1]=0ull; }
#pragma unroll 8
    for (int k = 0; k < 64; k++){
        ulonglong2 bp = *reinterpret_cast<const ulonglong2*>(&Ws[k*64 + tx*4]);
#pragma unroll
        for (int i = 0; i < 4; i++){
            float a = Ts[(ty*4+i)*65 + k];
            u64 ai = pk2(a, a);
            fma2(acc[i][0], ai, bp.x);
            fma2(acc[i][1], ai, bp.y);
        }
    }
    float bi0 = bb[h*64+tx*4+0], bi1 = bb[h*64+tx*4+1];
    float bi2 = bb[h*64+tx*4+2], bi3 = bb[h*64+tx*4+3];
#pragma unroll
    for (int i = 0; i < 4; i++){
        int m = m0 + ty*4 + i;
        int s = m >> 1, bq = m & 1;
        int bh = bq*NH + h;
        float v0,v1,v2,v3; up2(acc[i][0],v0,v1); up2(acc[i][1],v2,v3);
        v0 += bi0; v1 += bi1; v2 += bi2; v3 += bi3;

        __nv_bfloat16 h0 = __float2bfloat16_rn(v0);
        __nv_bfloat16 h1 = __float2bfloat16_rn(v1);
        __nv_bfloat16 h2 = __float2bfloat16_rn(v2);
        __nv_bfloat16 h3 = __float2bfloat16_rn(v3);
        __nv_bfloat16 l0 = __float2bfloat16_rn(v0 - __bfloat162float(h0));
        __nv_bfloat16 l1 = __float2bfloat16_rn(v1 - __bfloat162float(h1));
        __nv_bfloat16 l2 = __float2bfloat16_rn(v2 - __bfloat162float(h2));
        __nv_bfloat16 l3 = __float2bfloat16_rn(v3 - __bfloat162float(h3));

        __nv_bfloat16* ph = (mat==0) ? g_qhi : (mat==1 ? g_khi : g_vhi);
        __nv_bfloat16* pl = (mat==0) ? g_qlo : (mat==1 ? g_klo : g_vlo);
        size_t base = ((size_t)bh*SQ + s)*DH + tx*4;
        ph[base+0]=h0; ph[base+1]=h1; ph[base+2]=h2; ph[base+3]=h3;
        pl[base+0]=l0; pl[base+1]=l1; pl[base+2]=l2; pl[base+3]=l3;

        if (mat < 2){
            float rs = v0*v0 + v1*v1 + v2*v2 + v3*v3;
#pragma unroll
            for (int off = 8; off; off >>= 1)
                rs += __shfl_xor_sync(0xffffffffu, rs, off);
            if (tx == 0) g_sq[mat][(size_t)bh*SQ + s] = rs;
        }
    }
}

// ---------------------------------------------------------------------------
// Kernel 3: mma.sync bf16x3 attention.  CTA = 128 q-rows, 32 key tiles of 64.
// smem 109KB -> 2 CTAs/SM.
// ---------------------------------------------------------------------------
#define QK_ST 72     // bf16 row stride (36 words == 4 mod 32: conflict-free)
#define P_ST  72
#define SM_QSQ 0
#define SM_KSQ 512
#define SM_QHI 1024
#define SM_QLO (SM_QHI + 18432)
#define SM_KHI (SM_QLO + 18432)
#define SM_KLO (SM_KHI + 9216)
#define SM_VHI (SM_KLO + 9216)
#define SM_VLO (SM_VHI + 9216)
#define SM_PHI (SM_VLO + 9216)
#define SM_PLO (SM_PHI + 18432)
#define SM_TOTAL (SM_PLO + 18432)   // 111616 bytes

__global__ void __launch_bounds__(256, 2) k_attn(float* __restrict__ out)
{
    extern __shared__ __align__(16) char sm[];
    const uint32_t sb = s2u(sm);
    const int tid = threadIdx.x, lid = tid & 31, wid = tid >> 5;
    const int bh = blockIdx.y, b = bh >> 4, h = bh & 15;
    const int s0 = blockIdx.x * 128;

    // ---- resident Q tiles (hi/lo) + qsq ----
    {
        const __nv_bfloat16* qh = g_qhi + ((size_t)bh*SQ + s0)*DH;
        const __nv_bfloat16* ql = g_qlo + ((size_t)bh*SQ + s0)*DH;
#pragma unroll
        for (int it = 0; it < 4; it++){
            int e = tid + it*256;             // 1024 x 16B chunks
            int r = e >> 3, c8 = (e & 7)*8;
            uint32_t so = (uint32_t)(r*QK_ST + c8)*2u;
            *reinterpret_cast<uint4*>(sm + SM_QHI + so) =
                *reinterpret_cast<const uint4*>(qh + (size_t)r*DH + c8);
            *reinterpret_cast<uint4*>(sm + SM_QLO + so) =
                *reinterpret_cast<const uint4*>(ql + (size_t)r*DH + c8);
        }
        if (tid < 128)
            reinterpret_cast<float*>(sm + SM_QSQ)[tid] = g_sq[0][(size_t)bh*SQ + s0 + tid];
    }

    const int m0 = (wid & 3) * 32;   // warp M base (both GEMMs)
    const int n1 = (wid >> 2) * 32;  // GEMM1 N base (key cols, tile 64 wide)
    const int n2 = (wid >> 2) * 32;  // GEMM2 N base (head-dim cols)

    float acc2[2][4][4];
#pragma unroll
    for (int mt = 0; mt < 2; mt++)
#pragma unroll
        for (int nt = 0; nt < 4; nt++)
#pragma unroll
            for (int q = 0; q < 4; q++) acc2[mt][nt][q] = 0.0f;

    for (int kt = 0; kt < 32; kt++){
        __syncthreads();   // prev GEMM2 done reading P/V; K/V free
        // ---- load K, V (hi/lo) + ksq : 64 key rows ----
        {
            const size_t off = ((size_t)bh*SQ + kt*64)*DH;
#pragma unroll
            for (int it = 0; it < 2; it++){
                int e = tid + it*256;             // 512 x 16B chunks
                int r = e >> 3, c8 = (e & 7)*8;
                uint32_t so = (uint32_t)(r*QK_ST + c8)*2u;
                size_t go = off + (size_t)r*DH + c8;
                *reinterpret_cast<uint4*>(sm + SM_KHI + so) = *reinterpret_cast<const uint4*>(g_khi + go);
                *reinterpret_cast<uint4*>(sm + SM_KLO + so) = *reinterpret_cast<const uint4*>(g_klo + go);
                *reinterpret_cast<uint4*>(sm + SM_VHI + so) = *reinterpret_cast<const uint4*>(g_vhi + go);
                *reinterpret_cast<uint4*>(sm + SM_VLO + so) = *reinterpret_cast<const uint4*>(g_vlo + go);
            }
            if (tid < 64)
                reinterpret_cast<float*>(sm + SM_KSQ)[tid] = g_sq[1][(size_t)bh*SQ + kt*64 + tid];
        }
        __syncthreads();

        // ---- GEMM1: qk = Q.K^T  (bf16 x3 passes) ----
        float acc1[2][4][4];
#pragma unroll
        for (int mt = 0; mt < 2; mt++)
#pragma unroll
            for (int nt = 0; nt < 4; nt++)
#pragma unroll
                for (int q = 0; q < 4; q++) acc1[mt][nt][q] = 0.0f;

#pragma unroll
        for (int p = 0; p < 3; p++){
            const uint32_t Ab = sb + ((p == 2) ? SM_QLO : SM_QHI);
            const uint32_t Bb = sb + ((p == 1) ? SM_KLO : SM_KHI);
#pragma unroll
            for (int ks = 0; ks < 4; ks++){
                const int d0 = ks*16;
                uint32_t a[2][4];
#pragma unroll
                for (int mt = 0; mt < 2; mt++){
                    int row = m0 + mt*16 + (lid & 15);
                    int col = d0 + ((lid >> 4) << 3);
                    ldmx4(a[mt][0], a[mt][1], a[mt][2], a[mt][3],
                          Ab + (uint32_t)(row*QK_ST + col)*2u);
                }
#pragma unroll
                for (int ntp = 0; ntp < 2; ntp++){
                    int row = n1 + ntp*16 + (lid & 7) + ((lid >> 4) << 3);
                    int col = d0 + (((lid >> 3) & 1) << 3);
                    uint32_t r0, r1, r2, r3;
                    ldmx4(r0, r1, r2, r3, Bb + (uint32_t)(row*QK_ST + col)*2u);
#pragma unroll
                    for (int mt = 0; mt < 2; mt++){
                        mma16816(acc1[mt][2*ntp],   a[mt], r0, r1);
                        mma16816(acc1[mt][2*ntp+1], a[mt], r2, r3);
                    }
                }
            }
        }

        // ---- epilogue: scores -> gmem, P = exp(score) split hi/lo -> smem ----
        {
            const float* qsq = reinterpret_cast<const float*>(sm + SM_QSQ);
            const float* ksq = reinterpret_cast<const float*>(sm + SM_KSQ);
#pragma unroll
            for (int mt = 0; mt < 2; mt++){
                int rlo = m0 + mt*16 + (lid >> 2);
                float q0 = qsq[rlo], q1 = qsq[rlo + 8];
                float* sr0 = out + CTXE + ((size_t)bh*SQ + (size_t)(s0 + rlo))*SQ + kt*64;
                float* sr1 = sr0 + (size_t)8*SQ;
#pragma unroll
                for (int nt = 0; nt < 4; nt++){
                    int col = n1 + nt*8 + 2*(lid & 3);
                    float k0 = ksq[col], k1 = ksq[col+1];
                    float s00 = fmaf(0.125f, acc1[mt][nt][0], -0.0625f*(q0 + k0));
                    float s01 = fmaf(0.125f, acc1[mt][nt][1], -0.0625f*(q0 + k1));
                    float s10 = fmaf(0.125f, acc1[mt][nt][2], -0.0625f*(q1 + k0));
                    float s11 = fmaf(0.125f, acc1[mt][nt][3], -0.0625f*(q1 + k1));
                    *reinterpret_cast<float2*>(sr0 + col) = make_float2(s00, s01);
                    *reinterpret_cast<float2*>(sr1 + col) = make_float2(s10, s11);
                    uint32_t hw, lw;
                    split2(__expf(s00), __expf(s01), hw, lw);
                    *reinterpret_cast<uint32_t*>(sm + SM_PHI + (uint32_t)(rlo*P_ST + col)*2u) = hw;
                    *reinterpret_cast<uint32_t*>(sm + SM_PLO + (uint32_t)(rlo*P_ST + col)*2u) = lw;
                    split2(__expf(s10), __expf(s11), hw, lw);
                    *reinterpret_cast<uint32_t*>(sm + SM_PHI + (uint32_t)((rlo+8)*P_ST + col)*2u) = hw;
                    *reinterpret_cast<uint32_t*>(sm + SM_PLO + (uint32_t)((rlo+8)*P_ST + col)*2u) = lw;
                }
            }
        }
        __syncthreads();

        // ---- GEMM2: ctx += P.V  (bf16 x3 passes; V via ldmatrix.trans) ----
#pragma unroll
        for (int p = 0; p < 3; p++){
            const uint32_t Ab = sb + ((p == 2) ? SM_PLO : SM_PHI);
            const uint32_t Bb = sb + ((p == 1) ? SM_VLO : SM_VHI);
#pragma unroll
            for (int ks = 0; ks < 4; ks++){
                const int t0 = ks*16;
                uint32_t a[2][4];
#pragma unroll
                for (int mt = 0; mt < 2; mt++){
                    int row = m0 + mt*16 + (lid & 15);
                    int col = t0 + ((lid >> 4) << 3);
                    ldmx4(a[mt][0], a[mt][1], a[mt][2], a[mt][3],
                          Ab + (uint32_t)(row*P_ST + col)*2u);
                }
#pragma unroll
                for (int dtp = 0; dtp < 2; dtp++){
                    int row = t0 + (lid & 7) + (((lid >> 3) & 1) << 3);
                    int col = n2 + dtp*16 + ((lid >> 4) << 3);
                    uint32_t r0, r1, r2, r3;
                    ldmx4t(r0, r1, r2, r3, Bb + (uint32_t)(row*QK_ST + col)*2u);
#pragma unroll
                    for (int mt = 0; mt < 2; mt++){
                        mma16816(acc2[mt][2*dtp],   a[mt], r0, r1);
                        mma16816(acc2[mt][2*dtp+1], a[mt], r2, r3);
                    }
                }
            }
        }
    }

    // ---- context epilogue: [s, b, h*64+d] ----
#pragma unroll
    for (int mt = 0; mt < 2; mt++){
        int rlo = m0 + mt*16 + (lid >> 2);
        float* o0 = out + (size_t)(s0 + rlo)*(BB*HID) + (size_t)b*HID + h*DH;
        float* o1 = o0 + (size_t)8*(BB*HID);
#pragma unroll
        for (int nt = 0; nt < 4; nt++){
            int col = n2 + nt*8 + 2*(lid & 3);
            *reinterpret_cast<float2*>(o0 + col) = make_float2(acc2[mt][nt][0], acc2[mt][nt][1]);
            *reinterpret_cast<float2*>(o1 + col) = make_float2(acc2[mt][nt][2], acc2[mt][nt][3]);
        }
    }
}

// ---------------------------------------------------------------------------
extern "C" void kernel_launch(void* const* d_in, const int* in_sizes, int n_in,
                              void* d_out, int out_size)
{
    const float* x   = (const float*)d_in[0];
    const float* wqa = (const float*)d_in[1];
    const float* bqa = (const float*)d_in[2];
    const float* wqb = (const float*)d_in[3];
    const float* bqb = (const float*)d_in[4];
    const float* wka = (const float*)d_in[5];
    const float* bka = (const float*)d_in[6];
    const float* wkb = (const float*)d_in[7];
    const float* bkb = (const float*)d_in[8];
    const float* wva = (const float*)d_in[9];
    const float* bva = (const float*)d_in[10];
    const float* wvb = (const float*)d_in[11];
    const float* bvb = (const float*)d_in[12];
    float* out = (float*)d_out;

    cudaFuncSetAttribute(k_attn, cudaFuncAttributeMaxDynamicSharedMemorySize, SM_TOTAL);

    k_proja<<<dim3(64, 3, 4), 256>>>(x, wqa, bqa, wka, bka, wva, bva);
    k_projb<<<dim3(64, 16, 3), 256>>>(wqb, bqb, wkb, bkb, wvb, bvb);
    k_attn<<<dim3(16, 32), 256, SM_TOTAL>>>(out);
}

// round 10
// speedup vs baseline: 3.3546x; 1.1492x over previous
#include <cuda_runtime.h>
#include <cuda_bf16.h>
#include <cstdint>

#define SQ   2048
#define BB   2
#define HID  1024
#define NH   16
#define DH   64
#define RK   64
#define NT   (SQ*BB)
#define BHN  (BB*NH)
#define CTXE ((size_t)SQ*BB*HID)

// ---------------- device scratch (no allocation allowed) ----------------
__device__ float g_tp[3][4][NT*RK];        // A-stage K-split partials
__device__ float g_sq[2][BHN*SQ];          // ||q||^2, ||k||^2 (fp32 exact)
__device__ __nv_bfloat16 g_qhi[BHN*SQ*DH], g_qlo[BHN*SQ*DH];
__device__ __nv_bfloat16 g_khi[BHN*SQ*DH], g_klo[BHN*SQ*DH];
__device__ __nv_bfloat16 g_vhi[BHN*SQ*DH], g_vlo[BHN*SQ*DH];

typedef unsigned long long u64;

__device__ __forceinline__ u64 pk2(float a, float b){
    u64 r; asm("mov.b64 %0,{%1,%2};" : "=l"(r) : "f"(a), "f"(b)); return r;
}
__device__ __forceinline__ void up2(u64 v, float& a, float& b){
    asm("mov.b64 {%0,%1},%2;" : "=f"(a), "=f"(b) : "l"(v));
}
__device__ __forceinline__ void fma2(u64& d, u64 a, u64 b){
    asm("fma.rn.f32x2 %0,%1,%2,%0;" : "+l"(d) : "l"(a), "l"(b));
}
__device__ __forceinline__ uint32_t s2u(const void* p){
    uint32_t a;
    asm("{ .reg .u64 t; cvta.to.shared.u64 t, %1; cvt.u32.u64 %0, t; }" : "=r"(a) : "l"(p));
    return a;
}

// ---------------- mma.sync helpers (baseline ISA) ------
__device__ __forceinline__ void ldmx4(uint32_t& r0, uint32_t& r1, uint32_t& r2, uint32_t& r3,
                                      uint32_t addr){
    asm volatile("ldmatrix.sync.aligned.m8n8.x4.shared.b16 {%0,%1,%2,%3}, [%4];"
        : "=r"(r0), "=r"(r1), "=r"(r2), "=r"(r3) : "r"(addr));
}
__device__ __forceinline__ void ldmx4t(uint32_t& r0, uint32_t& r1, uint32_t& r2, uint32_t& r3,
                                       uint32_t addr){
    asm volatile("ldmatrix.sync.aligned.m8n8.x4.trans.shared.b16 {%0,%1,%2,%3}, [%4];"
        : "=r"(r0), "=r"(r1), "=r"(r2), "=r"(r3) : "r"(addr));
}
__device__ __forceinline__ void mma16816(float* d, const uint32_t* a, uint32_t b0, uint32_t b1){
    asm volatile("mma.sync.aligned.m16n8k16.row.col.f32.bf16.bf16.f32 "
        "{%0,%1,%2,%3},{%4,%5,%6,%7},{%8,%9},{%0,%1,%2,%3};"
        : "+f"(d[0]), "+f"(d[1]), "+f"(d[2]), "+f"(d[3])
        : "r"(a[0]), "r"(a[1]), "r"(a[2]), "r"(a[3]), "r"(b0), "r"(b1));
}
__device__ __forceinline__ void split2(float x, float y, uint32_t& hi, uint32_t& lo){
    __nv_bfloat16 hx = __float2bfloat16_rn(x), hy = __float2bfloat16_rn(y);
    __nv_bfloat16 lx = __float2bfloat16_rn(x - __bfloat162float(hx));
    __nv_bfloat16 ly = __float2bfloat16_rn(y - __bfloat162float(hy));
    __nv_bfloat162 hp; hp.x = hx; hp.y = hy;
    __nv_bfloat162 lp; lp.x = lx; lp.y = ly;
    hi = *reinterpret_cast<uint32_t*>(&hp);
    lo = *reinterpret_cast<uint32_t*>(&lp);
}
__device__ __forceinline__ void cpa16(uint32_t dst, const void* src){
    asm volatile("cp.async.cg.shared.global [%0], [%1], 16;" :: "r"(dst), "l"(src));
}
#define CP_COMMIT() asm volatile("cp.async.commit_group;")
#define CP_WAIT(n)  asm volatile("cp.async.wait_group %0;" :: "n"(n))

// ---------------------------------------------------------------------------
// Kernel 1: A-stage partial  t_kc = x[:, kc*256:(kc+1)*256] @ wa[kc...] (+ba at kc0)
// ---------------------------------------------------------------------------
__global__ void __launch_bounds__(256) k_proja(
    const float* __restrict__ x,
    const float* __restrict__ w0, const float* __restrict__ b0,
    const float* __restrict__ w1, const float* __restrict__ b1,
    const float* __restrict__ w2, const float* __restrict__ b2)
{
    __shared__ float Xs[64*65];
    __shared__ __align__(16) float Ws[64*64];
    const int mat = blockIdx.y;
    const int kc  = blockIdx.z;
    const float* wa = (mat==0) ? w0 : (mat==1 ? w1 : w2);
    const float* ba = (mat==0) ? b0 : (mat==1 ? b1 : b2);
    const int m0 = blockIdx.x * 64;
    const int tid = threadIdx.x, tx = tid & 15, ty = tid >> 4;

    u64 acc[4][2];
#pragma unroll
    for (int i = 0; i < 4; i++){ acc[i][0] = 0ull; acc[i][1] = 0ull; }

    for (int k0 = kc*256; k0 < kc*256 + 256; k0 += 64){
        __syncthreads();
#pragma unroll
        for (int it = 0; it < 4; it++){
            int e = tid + it*256;
            int r = e >> 4, c = (e & 15)*4;
            float4 v = *reinterpret_cast<const float4*>(x + (size_t)(m0+r)*HID + k0 + c);
            Xs[r*65+c+0]=v.x; Xs[r*65+c+1]=v.y; Xs[r*65+c+2]=v.z; Xs[r*65+c+3]=v.w;
            *reinterpret_cast<float4*>(&Ws[r*64+c]) =
                *reinterpret_cast<const float4*>(wa + (size_t)(k0+r)*RK + c);
        }
        __syncthreads();
#pragma unroll 8
        for (int k = 0; k < 64; k++){
            ulonglong2 bp = *reinterpret_cast<const ulonglong2*>(&Ws[k*64 + tx*4]);
#pragma unroll
            for (int i = 0; i < 4; i++){
                float a = Xs[(ty*4+i)*65 + k];
                u64 ai = pk2(a, a);
                fma2(acc[i][0], ai, bp.x);
                fma2(acc[i][1], ai, bp.y);
            }
        }
    }
    float* outp = g_tp[mat][kc];
    float bi0 = 0.f, bi1 = 0.f, bi2 = 0.f, bi3 = 0.f;
    if (kc == 0){ bi0 = ba[tx*4+0]; bi1 = ba[tx*4+1]; bi2 = ba[tx*4+2]; bi3 = ba[tx*4+3]; }
#pragma unroll
    for (int i = 0; i < 4; i++){
        float v0,v1,v2,v3; up2(acc[i][0],v0,v1); up2(acc[i][1],v2,v3);
        *reinterpret_cast<float4*>(outp + (size_t)(m0+ty*4+i)*RK + tx*4)
            = make_float4(v0+bi0, v1+bi1, v2+bi2, v3+bi3);
    }
}

// ---------------------------------------------------------------------------
// Kernel 2: B-stage + bf16 hi/lo split emit + ||row||^2.
// ---------------------------------------------------------------------------
__global__ void __launch_bounds__(256) k_projb(
    const float* __restrict__ w0, const float* __restrict__ b0,
    const float* __restrict__ w1, const float* __restrict__ b1,
    const float* __restrict__ w2, const float* __restrict__ b2)
{
    __shared__ float Ts[64*65];
    __shared__ __align__(16) float Ws[64*64];
    const int mat = blockIdx.z;
    const int h   = blockIdx.y;
    const int m0  = blockIdx.x * 64;
    const float* wb = (mat==0) ? w0 : (mat==1 ? w1 : w2);
    const float* bb = (mat==0) ? b0 : (mat==1 ? b1 : b2);
    const int tid = threadIdx.x, tx = tid & 15, ty = tid >> 4;

#pragma unroll
    for (int it = 0; it < 4; it++){
        int e = tid + it*256;
        int r = e >> 4, c = (e & 15)*4;
        size_t off = (size_t)(m0+r)*RK + c;
        float4 v0 = *reinterpret_cast<const float4*>(g_tp[mat][0] + off);
        float4 v1 = *reinterpret_cast<const float4*>(g_tp[mat][1] + off);
        float4 v2 = *reinterpret_cast<const float4*>(g_tp[mat][2] + off);
        float4 v3 = *reinterpret_cast<const float4*>(g_tp[mat][3] + off);
        Ts[r*65+c+0] = v0.x + v1.x + v2.x + v3.x;
        Ts[r*65+c+1] = v0.y + v1.y + v2.y + v3.y;
        Ts[r*65+c+2] = v0.z + v1.z + v2.z + v3.z;
        Ts[r*65+c+3] = v0.w + v1.w + v2.w + v3.w;
        *reinterpret_cast<float4*>(&Ws[r*64+c]) =
            *reinterpret_cast<const float4*>(wb + (size_t)r*HID + h*64 + c);
    }
    __syncthreads();

    u64 acc[4][2];
#pragma unroll
    for (int i = 0; i < 4; i++){ acc[i][0]=0ull; acc[i][1]=0ull; }
#pragma unroll 8
    for (int k = 0; k < 64; k++){
        ulonglong2 bp = *reinterpret_cast<const ulonglong2*>(&Ws[k*64 + tx*4]);
#pragma unroll
        for (int i = 0; i < 4; i++){
            float a = Ts[(ty*4+i)*65 + k];
            u64 ai = pk2(a, a);
            fma2(acc[i][0], ai, bp.x);
            fma2(acc[i][1], ai, bp.y);
        }
    }
    float bi0 = bb[h*64+tx*4+0], bi1 = bb[h*64+tx*4+1];
    float bi2 = bb[h*64+tx*4+2], bi3 = bb[h*64+tx*4+3];
#pragma unroll
    for (int i = 0; i < 4; i++){
        int m = m0 + ty*4 + i;
        int s = m >> 1, bq = m & 1;
        int bh = bq*NH + h;
        float v0,v1,v2,v3; up2(acc[i][0],v0,v1); up2(acc[i][1],v2,v3);
        v0 += bi0; v1 += bi1; v2 += bi2; v3 += bi3;

        __nv_bfloat16 h0 = __float2bfloat16_rn(v0);
        __nv_bfloat16 h1 = __float2bfloat16_rn(v1);
        __nv_bfloat16 h2 = __float2bfloat16_rn(v2);
        __nv_bfloat16 h3 = __float2bfloat16_rn(v3);
        __nv_bfloat16 l0 = __float2bfloat16_rn(v0 - __bfloat162float(h0));
        __nv_bfloat16 l1 = __float2bfloat16_rn(v1 - __bfloat162float(h1));
        __nv_bfloat16 l2 = __float2bfloat16_rn(v2 - __bfloat162float(h2));
        __nv_bfloat16 l3 = __float2bfloat16_rn(v3 - __bfloat162float(h3));

        __nv_bfloat16* ph = (mat==0) ? g_qhi : (mat==1 ? g_khi : g_vhi);
        __nv_bfloat16* pl = (mat==0) ? g_qlo : (mat==1 ? g_klo : g_vlo);
        size_t base = ((size_t)bh*SQ + s)*DH + tx*4;
        ph[base+0]=h0; ph[base+1]=h1; ph[base+2]=h2; ph[base+3]=h3;
        pl[base+0]=l0; pl[base+1]=l1; pl[base+2]=l2; pl[base+3]=l3;

        if (mat < 2){
            float rs = v0*v0 + v1*v1 + v2*v2 + v3*v3;
#pragma unroll
            for (int off = 8; off; off >>= 1)
                rs += __shfl_xor_sync(0xffffffffu, rs, off);
            if (tx == 0) g_sq[mat][(size_t)bh*SQ + s] = rs;
        }
    }
}

// ---------------------------------------------------------------------------
// Kernel 3: mma.sync bf16x3 attention.  CTA = 128 q-rows, 32 key tiles of 64.
// cp.async loads (V group overlapped with GEMM1); fragment-hoisted passes.
// ---------------------------------------------------------------------------
#define QK_ST 72
#define P_ST  72
#define SM_QSQ 0
#define SM_KSQ 512
#define SM_QHI 1024
#define SM_QLO (SM_QHI + 18432)
#define SM_KHI (SM_QLO + 18432)
#define SM_KLO (SM_KHI + 9216)
#define SM_VHI (SM_KLO + 9216)
#define SM_VLO (SM_VHI + 9216)
#define SM_PHI (SM_VLO + 9216)
#define SM_PLO (SM_PHI + 18432)
#define SM_TOTAL (SM_PLO + 18432)   // 111616 bytes

__global__ void __launch_bounds__(256, 2) k_attn(float* __restrict__ out)
{
    extern __shared__ __align__(16) char sm[];
    const uint32_t sb = s2u(sm);
    const int tid = threadIdx.x, lid = tid & 31, wid = tid >> 5;
    const int bh = blockIdx.y, b = bh >> 4, h = bh & 15;
    const int s0 = blockIdx.x * 128;

    // ---- resident Q tiles (hi/lo) + qsq ----
    {
        const __nv_bfloat16* qh = g_qhi + ((size_t)bh*SQ + s0)*DH;
        const __nv_bfloat16* ql = g_qlo + ((size_t)bh*SQ + s0)*DH;
#pragma unroll
        for (int it = 0; it < 4; it++){
            int e = tid + it*256;
            int r = e >> 3, c8 = (e & 7)*8;
            uint32_t so = (uint32_t)(r*QK_ST + c8)*2u;
            *reinterpret_cast<uint4*>(sm + SM_QHI + so) =
                *reinterpret_cast<const uint4*>(qh + (size_t)r*DH + c8);
            *reinterpret_cast<uint4*>(sm + SM_QLO + so) =
                *reinterpret_cast<const uint4*>(ql + (size_t)r*DH + c8);
        }
        if (tid < 128)
            reinterpret_cast<float*>(sm + SM_QSQ)[tid] = g_sq[0][(size_t)bh*SQ + s0 + tid];
    }

    const int m0 = (wid & 3) * 32;
    const int n1 = (wid >> 2) * 32;
    const int n2 = (wid >> 2) * 32;

    float acc2[2][4][4];
#pragma unroll
    for (int mt = 0; mt < 2; mt++)
#pragma unroll
        for (int nt = 0; nt < 4; nt++)
#pragma unroll
            for (int q = 0; q < 4; q++) acc2[mt][nt][q] = 0.0f;

    for (int kt = 0; kt < 32; kt++){
        __syncthreads();   // prev GEMM2 done with V/P; buffers free
        // ---- cp.async loads: group A = K(hi/lo)+ksq, group B = V(hi/lo) ----
        {
            const size_t off = ((size_t)bh*SQ + kt*64)*DH;
#pragma unroll
            for (int it = 0; it < 2; it++){
                int e = tid + it*256;
                int r = e >> 3, c8 = (e & 7)*8;
                uint32_t so = (uint32_t)(r*QK_ST + c8)*2u;
                size_t go = off + (size_t)r*DH + c8;
                cpa16(sb + SM_KHI + so, g_khi + go);
                cpa16(sb + SM_KLO + so, g_klo + go);
            }
            if (tid < 16)
                cpa16(sb + SM_KSQ + (uint32_t)tid*16u,
                      g_sq[1] + (size_t)bh*SQ + kt*64 + tid*4);
            CP_COMMIT();
#pragma unroll
            for (int it = 0; it < 2; it++){
                int e = tid + it*256;
                int r = e >> 3, c8 = (e & 7)*8;
                uint32_t so = (uint32_t)(r*QK_ST + c8)*2u;
                size_t go = off + (size_t)r*DH + c8;
                cpa16(sb + SM_VHI + so, g_vhi + go);
                cpa16(sb + SM_VLO + so, g_vlo + go);
            }
            CP_COMMIT();
            CP_WAIT(1);        // K + ksq landed; V still in flight
        }
        __syncthreads();

        // ---- GEMM1: qk = Q.K^T, 3 bf16 passes from hoisted fragments ----
        float acc1[2][4][4];
#pragma unroll
        for (int mt = 0; mt < 2; mt++)
#pragma unroll
            for (int nt = 0; nt < 4; nt++)
#pragma unroll
                for (int q = 0; q < 4; q++) acc1[mt][nt][q] = 0.0f;

#pragma unroll
        for (int ks = 0; ks < 4; ks++){
            const int d0 = ks*16;
            uint32_t aH[2][4], aL[2][4];
#pragma unroll
            for (int mt = 0; mt < 2; mt++){
                int row = m0 + mt*16 + (lid & 15);
                int col = d0 + ((lid >> 4) << 3);
                uint32_t ao = (uint32_t)(row*QK_ST + col)*2u;
                ldmx4(aH[mt][0], aH[mt][1], aH[mt][2], aH[mt][3], sb + SM_QHI + ao);
                ldmx4(aL[mt][0], aL[mt][1], aL[mt][2], aL[mt][3], sb + SM_QLO + ao);
            }
#pragma unroll
            for (int ntp = 0; ntp < 2; ntp++){
                int row = n1 + ntp*16 + (lid & 7) + ((lid >> 4) << 3);
                int col = d0 + (((lid >> 3) & 1) << 3);
                uint32_t bo = (uint32_t)(row*QK_ST + col)*2u;
                uint32_t h0, h1, h2, h3, l0, l1, l2, l3;
                ldmx4(h0, h1, h2, h3, sb + SM_KHI + bo);
                ldmx4(l0, l1, l2, l3, sb + SM_KLO + bo);
#pragma unroll
                for (int mt = 0; mt < 2; mt++){
                    mma16816(acc1[mt][2*ntp],   aH[mt], h0, h1);
                    mma16816(acc1[mt][2*ntp+1], aH[mt], h2, h3);
                    mma16816(acc1[mt][2*ntp],   aH[mt], l0, l1);
                    mma16816(acc1[mt][2*ntp+1], aH[mt], l2, l3);
                    mma16816(acc1[mt][2*ntp],   aL[mt], h0, h1);
                    mma16816(acc1[mt][2*ntp+1], aL[mt], h2, h3);
                }
            }
        }

        // ---- epilogue: scores -> gmem, P = exp(score) split hi/lo -> smem ----
        {
            const float* qsq = reinterpret_cast<const float*>(sm + SM_QSQ);
            const float* ksq = reinterpret_cast<const float*>(sm + SM_KSQ);
#pragma unroll
            for (int mt = 0; mt < 2; mt++){
                int rlo = m0 + mt*16 + (lid >> 2);
                float q0 = qsq[rlo], q1 = qsq[rlo + 8];
                float* sr0 = out + CTXE + ((size_t)bh*SQ + (size_t)(s0 + rlo))*SQ + kt*64;
                float* sr1 = sr0 + (size_t)8*SQ;
#pragma unroll
                for (int nt = 0; nt < 4; nt++){
                    int col = n1 + nt*8 + 2*(lid & 3);
                    float k0 = ksq[col], k1 = ksq[col+1];
                    float s00 = fmaf(0.125f, acc1[mt][nt][0], -0.0625f*(q0 + k0));
                    float s01 = fmaf(0.125f, acc1[mt][nt][1], -0.0625f*(q0 + k1));
                    float s10 = fmaf(0.125f, acc1[mt][nt][2], -0.0625f*(q1 + k0));
                    float s11 = fmaf(0.125f, acc1[mt][nt][3], -0.0625f*(q1 + k1));
                    *reinterpret_cast<float2*>(sr0 + col) = make_float2(s00, s01);
                    *reinterpret_cast<float2*>(sr1 + col) = make_float2(s10, s11);
                    uint32_t hw, lw;
                    split2(__expf(s00), __expf(s01), hw, lw);
                    *reinterpret_cast<uint32_t*>(sm + SM_PHI + (uint32_t)(rlo*P_ST + col)*2u) = hw;
                    *reinterpret_cast<uint32_t*>(sm + SM_PLO + (uint32_t)(rlo*P_ST + col)*2u) = lw;
                    split2(__expf(s10), __expf(s11), hw, lw);
                    *reinterpret_cast<uint32_t*>(sm + SM_PHI + (uint32_t)((rlo+8)*P_ST + col)*2u) = hw;
                    *reinterpret_cast<uint32_t*>(sm + SM_PLO + (uint32_t)((rlo+8)*P_ST + col)*2u) = lw;
                }
            }
        }
        CP_WAIT(0);            // V landed
        __syncthreads();       // P visible to all warps

        // ---- GEMM2: ctx += P.V, 3 bf16 passes from hoisted fragments ----
#pragma unroll
        for (int ks = 0; ks < 4; ks++){
            const int t0 = ks*16;
            uint32_t aH[2][4], aL[2][4];
#pragma unroll
            for (int mt = 0; mt < 2; mt++){
                int row = m0 + mt*16 + (lid & 15);
                int col = t0 + ((lid >> 4) << 3);
                uint32_t ao = (uint32_t)(row*P_ST + col)*2u;
                ldmx4(aH[mt][0], aH[mt][1], aH[mt][2], aH[mt][3], sb + SM_PHI + ao);
                ldmx4(aL[mt][0], aL[mt][1], aL[mt][2], aL[mt][3], sb + SM_PLO + ao);
            }
#pragma unroll
            for (int dtp = 0; dtp < 2; dtp++){
                int row = t0 + (lid & 7) + (((lid >> 3) & 1) << 3);
                int col = n2 + dtp*16 + ((lid >> 4) << 3);
                uint32_t bo = (uint32_t)(row*QK_ST + col)*2u;
                uint32_t h0, h1, h2, h3, l0, l1, l2, l3;
                ldmx4t(h0, h1, h2, h3, sb + SM_VHI + bo);
                ldmx4t(l0, l1, l2, l3, sb + SM_VLO + bo);
#pragma unroll
                for (int mt = 0; mt < 2; mt++){
                    mma16816(acc2[mt][2*dtp],   aH[mt], h0, h1);
                    mma16816(acc2[mt][2*dtp+1], aH[mt], h2, h3);
                    mma16816(acc2[mt][2*dtp],   aH[mt], l0, l1);
                    mma16816(acc2[mt][2*dtp+1], aH[mt], l2, l3);
                    mma16816(acc2[mt][2*dtp],   aL[mt], h0, h1);
                    mma16816(acc2[mt][2*dtp+1], aL[mt], h2, h3);
                }
            }
        }
    }

    // ---- context epilogue: [s, b, h*64+d] ----
#pragma unroll
    for (int mt = 0; mt < 2; mt++){
        int rlo = m0 + mt*16 + (lid >> 2);
        float* o0 = out + (size_t)(s0 + rlo)*(BB*HID) + (size_t)b*HID + h*DH;
        float* o1 = o0 + (size_t)8*(BB*HID);
#pragma unroll
        for (int nt = 0; nt < 4; nt++){
            int col = n2 + nt*8 + 2*(lid & 3);
            *reinterpret_cast<float2*>(o0 + col) = make_float2(acc2[mt][nt][0], acc2[mt][nt][1]);
            *reinterpret_cast<float2*>(o1 + col) = make_float2(acc2[mt][nt][2], acc2[mt][nt][3]);
        }
    }
}

// ---------------------------------------------------------------------------
extern "C" void kernel_launch(void* const* d_in, const int* in_sizes, int n_in,
                              void* d_out, int out_size)
{
    const float* x   = (const float*)d_in[0];
    const float* wqa = (const float*)d_in[1];
    const float* bqa = (const float*)d_in[2];
    const float* wqb = (const float*)d_in[3];
    const float* bqb = (const float*)d_in[4];
    const float* wka = (const float*)d_in[5];
    const float* bka = (const float*)d_in[6];
    const float* wkb = (const float*)d_in[7];
    const float* bkb = (const float*)d_in[8];
    const float* wva = (const float*)d_in[9];
    const float* bva = (const float*)d_in[10];
    const float* wvb = (const float*)d_in[11];
    const float* bvb = (const float*)d_in[12];
    float* out = (float*)d_out;

    cudaFuncSetAttribute(k_attn, cudaFuncAttributeMaxDynamicSharedMemorySize, SM_TOTAL);

    k_proja<<<dim3(64, 3, 4), 256>>>(x, wqa, bqa, wka, bka, wva, bva);
    k_projb<<<dim3(64, 16, 3), 256>>>(wqb, bqb, wkb, bkb, wvb, bvb);
    k_attn<<<dim3(16, 32), 256, SM_TOTAL>>>(out);
}

// round 11
// speedup vs baseline: 3.4732x; 1.0353x over previous
#include <cuda_runtime.h>
#include <cuda_bf16.h>
#include <cstdint>

#define SQ   2048
#define BB   2
#define HID  1024
#define NH   16
#define DH   64
#define RK   64
#define NT   (SQ*BB)
#define BHN  (BB*NH)
#define CTXE ((size_t)SQ*BB*HID)

// ---------------- device scratch (no allocation allowed) ----------------
__device__ float g_tp[3][4][NT*RK];        // A-stage K-split partials
__device__ float g_sq[2][BHN*SQ];          // ||q||^2, ||k||^2 (fp32 exact)
__device__ __nv_bfloat16 g_qhi[BHN*SQ*DH], g_qlo[BHN*SQ*DH];
__device__ __nv_bfloat16 g_khi[BHN*SQ*DH], g_klo[BHN*SQ*DH];
__device__ __nv_bfloat16 g_vhi[BHN*SQ*DH], g_vlo[BHN*SQ*DH];

typedef unsigned long long u64;

__device__ __forceinline__ u64 pk2(float a, float b){
    u64 r; asm("mov.b64 %0,{%1,%2};" : "=l"(r) : "f"(a), "f"(b)); return r;
}
__device__ __forceinline__ void up2(u64 v, float& a, float& b){
    asm("mov.b64 {%0,%1},%2;" : "=f"(a), "=f"(b) : "l"(v));
}
__device__ __forceinline__ void fma2(u64& d, u64 a, u64 b){
    asm("fma.rn.f32x2 %0,%1,%2,%0;" : "+l"(d) : "l"(a), "l"(b));
}
__device__ __forceinline__ uint32_t s2u(const void* p){
    uint32_t a;
    asm("{ .reg .u64 t; cvta.to.shared.u64 t, %1; cvt.u32.u64 %0, t; }" : "=r"(a) : "l"(p));
    return a;
}

// ---------------- mma.sync helpers (baseline ISA) ------
__device__ __forceinline__ void ldmx4(uint32_t& r0, uint32_t& r1, uint32_t& r2, uint32_t& r3,
                                      uint32_t addr){
    asm volatile("ldmatrix.sync.aligned.m8n8.x4.shared.b16 {%0,%1,%2,%3}, [%4];"
        : "=r"(r0), "=r"(r1), "=r"(r2), "=r"(r3) : "r"(addr));
}
__device__ __forceinline__ void ldmx4t(uint32_t& r0, uint32_t& r1, uint32_t& r2, uint32_t& r3,
                                       uint32_t addr){
    asm volatile("ldmatrix.sync.aligned.m8n8.x4.trans.shared.b16 {%0,%1,%2,%3}, [%4];"
        : "=r"(r0), "=r"(r1), "=r"(r2), "=r"(r3) : "r"(addr));
}
__device__ __forceinline__ void mma16816(float* d, const uint32_t* a, uint32_t b0, uint32_t b1){
    asm volatile("mma.sync.aligned.m16n8k16.row.col.f32.bf16.bf16.f32 "
        "{%0,%1,%2,%3},{%4,%5,%6,%7},{%8,%9},{%0,%1,%2,%3};"
        : "+f"(d[0]), "+f"(d[1]), "+f"(d[2]), "+f"(d[3])
        : "r"(a[0]), "r"(a[1]), "r"(a[2]), "r"(a[3]), "r"(b0), "r"(b1));
}
// Packed bf16 hi/lo split: hi = packed bf16x2(x,y); lo = residuals.
__device__ __forceinline__ void split2(float x, float y, uint32_t& hi, uint32_t& lo){
    uint32_t h;
    asm("cvt.rn.bf16x2.f32 %0, %1, %2;" : "=r"(h) : "f"(y), "f"(x));  // {hi16=y, lo16=x}
    float xh = __uint_as_float(h << 16);
    float yh = __uint_as_float(h & 0xFFFF0000u);
    float xl = x - xh, yl = y - yh;
    uint32_t l;
    asm("cvt.rn.bf16x2.f32 %0, %1, %2;" : "=r"(l) : "f"(yl), "f"(xl));
    hi = h; lo = l;
}
__device__ __forceinline__ void cpa16(uint32_t dst, const void* src){
    asm volatile("cp.async.cg.shared.global [%0], [%1], 16;" :: "r"(dst), "l"(src));
}
#define CP_COMMIT() asm volatile("cp.async.commit_group;")
#define CP_WAIT(n)  asm volatile("cp.async.wait_group %0;" :: "n"(n))

// ---------------------------------------------------------------------------
// Kernel 1: A-stage, all 3 mats fused (x read once).
// grid (64 Mtiles, 4 kchunks), 256 threads, 64x64 tile, 4x4 micro per mat.
// ---------------------------------------------------------------------------
__global__ void __launch_bounds__(256) k_proja(
    const float* __restrict__ x,
    const float* __restrict__ w0, const float* __restrict__ b0,
    const float* __restrict__ w1, const float* __restrict__ b1,
    const float* __restrict__ w2, const float* __restrict__ b2)
{
    __shared__ float Xs[64*65];
    __shared__ __align__(16) float Ws[64*64];
    const int kc  = blockIdx.y;
    const int m0  = blockIdx.x * 64;
    const int tid = threadIdx.x, tx = tid & 15, ty = tid >> 4;

    const float* wptr[3] = { w0, w1, w2 };
    const float* bptr[3] = { b0, b1, b2 };

    u64 acc[3][4][2];
#pragma unroll
    for (int m = 0; m < 3; m++)
#pragma unroll
        for (int i = 0; i < 4; i++){ acc[m][i][0] = 0ull; acc[m][i][1] = 0ull; }

    for (int k0 = kc*256; k0 < kc*256 + 256; k0 += 64){
        __syncthreads();
#pragma unroll
        for (int it = 0; it < 4; it++){
            int e = tid + it*256;
            int r = e >> 4, c = (e & 15)*4;
            float4 v = *reinterpret_cast<const float4*>(x + (size_t)(m0+r)*HID + k0 + c);
            Xs[r*65+c+0]=v.x; Xs[r*65+c+1]=v.y; Xs[r*65+c+2]=v.z; Xs[r*65+c+3]=v.w;
        }
#pragma unroll
        for (int mat = 0; mat < 3; mat++){
            __syncthreads();
#pragma unroll
            for (int it = 0; it < 4; it++){
                int e = tid + it*256;
                int r = e >> 4, c = (e & 15)*4;
                *reinterpret_cast<float4*>(&Ws[r*64+c]) =
                    *reinterpret_cast<const float4*>(wptr[mat] + (size_t)(k0+r)*RK + c);
            }
            __syncthreads();
#pragma unroll 8
            for (int k = 0; k < 64; k++){
                ulonglong2 bp = *reinterpret_cast<const ulonglong2*>(&Ws[k*64 + tx*4]);
#pragma unroll
                for (int i = 0; i < 4; i++){
                    float a = Xs[(ty*4+i)*65 + k];
                    u64 ai = pk2(a, a);
                    fma2(acc[mat][i][0], ai, bp.x);
                    fma2(acc[mat][i][1], ai, bp.y);
                }
            }
        }
    }
#pragma unroll
    for (int mat = 0; mat < 3; mat++){
        float* outp = g_tp[mat][kc];
        float bi0 = 0.f, bi1 = 0.f, bi2 = 0.f, bi3 = 0.f;
        if (kc == 0){
            const float* ba = bptr[mat];
            bi0 = ba[tx*4+0]; bi1 = ba[tx*4+1]; bi2 = ba[tx*4+2]; bi3 = ba[tx*4+3];
        }
#pragma unroll
        for (int i = 0; i < 4; i++){
            float v0,v1,v2,v3; up2(acc[mat][i][0],v0,v1); up2(acc[mat][i][1],v2,v3);
            *reinterpret_cast<float4*>(outp + (size_t)(m0+ty*4+i)*RK + tx*4)
                = make_float4(v0+bi0, v1+bi1, v2+bi2, v3+bi3);
        }
    }
}

// ---------------------------------------------------------------------------
// Kernel 2: B-stage + bf16 hi/lo split emit + ||row||^2.
// ---------------------------------------------------------------------------
__global__ void __launch_bounds__(256) k_projb(
    const float* __restrict__ w0, const float* __restrict__ b0,
    const float* __restrict__ w1, const float* __restrict__ b1,
    const float* __restrict__ w2, const float* __restrict__ b2)
{
    __shared__ float Ts[64*65];
    __shared__ __align__(16) float Ws[64*64];
    const int mat = blockIdx.z;
    const int h   = blockIdx.y;
    const int m0  = blockIdx.x * 64;
    const float* wb = (mat==0) ? w0 : (mat==1 ? w1 : w2);
    const float* bb = (mat==0) ? b0 : (mat==1 ? b1 : b2);
    const int tid = threadIdx.x, tx = tid & 15, ty = tid >> 4;

#pragma unroll
    for (int it = 0; it < 4; it++){
        int e = tid + it*256;
        int r = e >> 4, c = (e & 15)*4;
        size_t off = (size_t)(m0+r)*RK + c;
        float4 v0 = *reinterpret_cast<const float4*>(g_tp[mat][0] + off);
        float4 v1 = *reinterpret_cast<const float4*>(g_tp[mat][1] + off);
        float4 v2 = *reinterpret_cast<const float4*>(g_tp[mat][2] + off);
        float4 v3 = *reinterpret_cast<const float4*>(g_tp[mat][3] + off);
        Ts[r*65+c+0] = v0.x + v1.x + v2.x + v3.x;
        Ts[r*65+c+1] = v0.y + v1.y + v2.y + v3.y;
        Ts[r*65+c+2] = v0.z + v1.z + v2.z + v3.z;
        Ts[r*65+c+3] = v0.w + v1.w + v2.w + v3.w;
        *reinterpret_cast<float4*>(&Ws[r*64+c]) =
            *reinterpret_cast<const float4*>(wb + (size_t)r*HID + h*64 + c);
    }
    __syncthreads();

    u64 acc[4][2];
#pragma unroll
    for (int i = 0; i < 4; i++){ acc[i][0]=0ull; acc[i][1]=0ull; }
#pragma unroll 8
    for (int k = 0; k < 64; k++){
        ulonglong2 bp = *reinterpret_cast<const ulonglong2*>(&Ws[k*64 + tx*4]);
#pragma unroll
        for (int i = 0; i < 4; i++){
            float a = Ts[(ty*4+i)*65 + k];
            u64 ai = pk2(a, a);
            fma2(acc[i][0], ai, bp.x);
            fma2(acc[i][1], ai, bp.y);
        }
    }
    float bi0 = bb[h*64+tx*4+0], bi1 = bb[h*64+tx*4+1];
    float bi2 = bb[h*64+tx*4+2], bi3 = bb[h*64+tx*4+3];
#pragma unroll
    for (int i = 0; i < 4; i++){
        int m = m0 + ty*4 + i;
        int s = m >> 1, bq = m & 1;
        int bh = bq*NH + h;
        float v0,v1,v2,v3; up2(acc[i][0],v0,v1); up2(acc[i][1],v2,v3);
        v0 += bi0; v1 += bi1; v2 += bi2; v3 += bi3;

        uint32_t hw01, lw01, hw23, lw23;
        split2(v0, v1, hw01, lw01);
        split2(v2, v3, hw23, lw23);

        __nv_bfloat16* ph = (mat==0) ? g_qhi : (mat==1 ? g_khi : g_vhi);
        __nv_bfloat16* pl = (mat==0) ? g_qlo : (mat==1 ? g_klo : g_vlo);
        size_t base = ((size_t)bh*SQ + s)*DH + tx*4;
        *reinterpret_cast<uint2*>(ph + base) = make_uint2(hw01, hw23);
        *reinterpret_cast<uint2*>(pl + base) = make_uint2(lw01, lw23);

        if (mat < 2){
            float rs = v0*v0 + v1*v1 + v2*v2 + v3*v3;
#pragma unroll
            for (int off = 8; off; off >>= 1)
                rs += __shfl_xor_sync(0xffffffffu, rs, off);
            if (tx == 0) g_sq[mat][(size_t)bh*SQ + s] = rs;
        }
    }
}

// ---------------------------------------------------------------------------
// Kernel 3: mma.sync bf16x3 attention.  CTA = 128 q-rows, 32 key tiles of 64.
// K(kt+1) prefetched behind GEMM2(kt); V(kt) behind GEMM1(kt).
// ---------------------------------------------------------------------------
#define QK_ST 72
#define P_ST  72
#define SM_QSQ 0
#define SM_KSQ 512
#define SM_QHI 1024
#define SM_QLO (SM_QHI + 18432)
#define SM_KHI (SM_QLO + 18432)
#define SM_KLO (SM_KHI + 9216)
#define SM_VHI (SM_KLO + 9216)
#define SM_VLO (SM_VHI + 9216)
#define SM_PHI (SM_VLO + 9216)
#define SM_PLO (SM_PHI + 18432)
#define SM_TOTAL (SM_PLO + 18432)   // 111616 bytes

__global__ void __launch_bounds__(256, 2) k_attn(float* __restrict__ out)
{
    extern __shared__ __align__(16) char sm[];
    const uint32_t sb = s2u(sm);
    const int tid = threadIdx.x, lid = tid & 31, wid = tid >> 5;
    const int bh = blockIdx.y, b = bh >> 4, h = bh & 15;
    const int s0 = blockIdx.x * 128;

    const size_t kvbase = (size_t)bh*SQ*DH;

    // per-thread K/V load coordinates (shared by prologue + loop)
    const int lr  = tid >> 3;            // row 0..31 (x2 iters -> 64)
    const int lc8 = (tid & 7) * 8;       // col base
    const uint32_t lso = (uint32_t)(lr*QK_ST + lc8)*2u;

    // ---- prologue: issue K(0)+ksq(0) ----
    {
        const size_t off = kvbase;
#pragma unroll
        for (int it = 0; it < 2; it++){
            uint32_t so = lso + (uint32_t)(it*32*QK_ST)*2u;
            size_t go = off + (size_t)(lr + it*32)*DH + lc8;
            cpa16(sb + SM_KHI + so, g_khi + go);
            cpa16(sb + SM_KLO + so, g_klo + go);
        }
        if (tid < 16)
            cpa16(sb + SM_KSQ + (uint32_t)tid*16u, g_sq[1] + (size_t)bh*SQ + tid*4);
        CP_COMMIT();
    }

    // ---- resident Q tiles (hi/lo) + qsq ----
    {
        const __nv_bfloat16* qh = g_qhi + ((size_t)bh*SQ + s0)*DH;
        const __nv_bfloat16* ql = g_qlo + ((size_t)bh*SQ + s0)*DH;
#pragma unroll
        for (int it = 0; it < 4; it++){
            int e = tid + it*256;
            int r = e >> 3, c8 = (e & 7)*8;
            uint32_t so = (uint32_t)(r*QK_ST + c8)*2u;
            *reinterpret_cast<uint4*>(sm + SM_QHI + so) =
                *reinterpret_cast<const uint4*>(qh + (size_t)r*DH + c8);
            *reinterpret_cast<uint4*>(sm + SM_QLO + so) =
                *reinterpret_cast<const uint4*>(ql + (size_t)r*DH + c8);
        }
        if (tid < 128)
            reinterpret_cast<float*>(sm + SM_QSQ)[tid] = g_sq[0][(size_t)bh*SQ + s0 + tid];
    }

    const int m0 = (wid & 3) * 32;
    const int n1 = (wid >> 2) * 32;
    const int n2 = (wid >> 2) * 32;

    float acc2[2][4][4];
#pragma unroll
    for (int mt = 0; mt < 2; mt++)
#pragma unroll
        for (int nt = 0; nt < 4; nt++)
#pragma unroll
            for (int q = 0; q < 4; q++) acc2[mt][nt][q] = 0.0f;

    for (int kt = 0; kt < 32; kt++){
        __syncthreads();                 // sync#1: GEMM2(kt-1) done -> V buffer free
        // ---- issue V(kt) ----
        {
            const size_t off = kvbase + (size_t)kt*64*DH;
#pragma unroll
            for (int it = 0; it < 2; it++){
                uint32_t so = lso + (uint32_t)(it*32*QK_ST)*2u;
                size_t go = off + (size_t)(lr + it*32)*DH + lc8;
                cpa16(sb + SM_VHI + so, g_vhi + go);
                cpa16(sb + SM_VLO + so, g_vlo + go);
            }
            CP_COMMIT();
        }
        CP_WAIT(1);                      // K(kt)+ksq landed; V(kt) in flight
        __syncthreads();                 // sync#2: K visible CTA-wide

        // ---- GEMM1: qk = Q.K^T, 3 bf16 passes from hoisted fragments ----
        float acc1[2][4][4];
#pragma unroll
        for (int mt = 0; mt < 2; mt++)
#pragma unroll
            for (int nt = 0; nt < 4; nt++)
#pragma unroll
                for (int q = 0; q < 4; q++) acc1[mt][nt][q] = 0.0f;

#pragma unroll
        for (int ks = 0; ks < 4; ks++){
            const int d0 = ks*16;
            uint32_t aH[2][4], aL[2][4];
#pragma unroll
            for (int mt = 0; mt < 2; mt++){
                int row = m0 + mt*16 + (lid & 15);
                int col = d0 + ((lid >> 4) << 3);
                uint32_t ao = (uint32_t)(row*QK_ST + col)*2u;
                ldmx4(aH[mt][0], aH[mt][1], aH[mt][2], aH[mt][3], sb + SM_QHI + ao);
                ldmx4(aL[mt][0], aL[mt][1], aL[mt][2], aL[mt][3], sb + SM_QLO + ao);
            }
#pragma unroll
            for (int ntp = 0; ntp < 2; ntp++){
                int row = n1 + ntp*16 + (lid & 7) + ((lid >> 4) << 3);
                int col = d0 + (((lid >> 3) & 1) << 3);
                uint32_t bo = (uint32_t)(row*QK_ST + col)*2u;
                uint32_t h0, h1, h2, h3, l0, l1, l2, l3;
                ldmx4(h0, h1, h2, h3, sb + SM_KHI + bo);
                ldmx4(l0, l1, l2, l3, sb + SM_KLO + bo);
#pragma unroll
                for (int mt = 0; mt < 2; mt++){
                    mma16816(acc1[mt][2*ntp],   aH[mt], h0, h1);
                    mma16816(acc1[mt][2*ntp+1], aH[mt], h2, h3);
                    mma16816(acc1[mt][2*ntp],   aH[mt], l0, l1);
                    mma16816(acc1[mt][2*ntp+1], aH[mt], l2, l3);
                    mma16816(acc1[mt][2*ntp],   aL[mt], h0, h1);
                    mma16816(acc1[mt][2*ntp+1], aL[mt], h2, h3);
                }
            }
        }

        // ---- epilogue: scores -> gmem, P = exp(score) split hi/lo -> smem ----
        {
            const float* qsq = reinterpret_cast<const float*>(sm + SM_QSQ);
            const float* ksq = reinterpret_cast<const float*>(sm + SM_KSQ);
#pragma unroll
            for (int mt = 0; mt < 2; mt++){
                int rlo = m0 + mt*16 + (lid >> 2);
                float q0 = qsq[rlo], q1 = qsq[rlo + 8];
                float* sr0 = out + CTXE + ((size_t)bh*SQ + (size_t)(s0 + rlo))*SQ + kt*64;
                float* sr1 = sr0 + (size_t)8*SQ;
#pragma unroll
                for (int nt = 0; nt < 4; nt++){
                    int col = n1 + nt*8 + 2*(lid & 3);
                    float k0 = ksq[col], k1 = ksq[col+1];
                    float s00 = fmaf(0.125f, acc1[mt][nt][0], -0.0625f*(q0 + k0));
                    float s01 = fmaf(0.125f, acc1[mt][nt][1], -0.0625f*(q0 + k1));
                    float s10 = fmaf(0.125f, acc1[mt][nt][2], -0.0625f*(q1 + k0));
                    float s11 = fmaf(0.125f, acc1[mt][nt][3], -0.0625f*(q1 + k1));
                    *reinterpret_cast<float2*>(sr0 + col) = make_float2(s00, s01);
                    *reinterpret_cast<float2*>(sr1 + col) = make_float2(s10, s11);
                    uint32_t hw, lw;
                    split2(__expf(s00), __expf(s01), hw, lw);
                    *reinterpret_cast<uint32_t*>(sm + SM_PHI + (uint32_t)(rlo*P_ST + col)*2u) = hw;
                    *reinterpret_cast<uint32_t*>(sm + SM_PLO + (uint32_t)(rlo*P_ST + col)*2u) = lw;
                    split2(__expf(s10), __expf(s11), hw, lw);
                    *reinterpret_cast<uint32_t*>(sm + SM_PHI + (uint32_t)((rlo+8)*P_ST + col)*2u) = hw;
                    *reinterpret_cast<uint32_t*>(sm + SM_PLO + (uint32_t)((rlo+8)*P_ST + col)*2u) = lw;
                }
            }
        }
        CP_WAIT(0);            // V(kt) landed
        __syncthreads();       // sync#3: P visible; GEMM1 done with K buffer

        // ---- prefetch K(kt+1)+ksq behind GEMM2 ----
        if (kt + 1 < 32){
            const size_t off = kvbase + (size_t)(kt+1)*64*DH;
#pragma unroll
            for (int it = 0; it < 2; it++){
                uint32_t so = lso + (uint32_t)(it*32*QK_ST)*2u;
                size_t go = off + (size_t)(lr + it*32)*DH + lc8;
                cpa16(sb + SM_KHI + so, g_khi + go);
                cpa16(sb + SM_KLO + so, g_klo + go);
            }
            if (tid < 16)
                cpa16(sb + SM_KSQ + (uint32_t)tid*16u,
                      g_sq[1] + (size_t)bh*SQ + (kt+1)*64 + tid*4);
            CP_COMMIT();
        } else {
            CP_COMMIT();       // keep group parity for CP_WAIT(1) at loop head
        }

        // ---- GEMM2: ctx += P.V, 3 bf16 passes from hoisted fragments ----
#pragma unroll
        for (int ks = 0; ks < 4; ks++){
            const int t0 = ks*16;
            uint32_t aH[2][4], aL[2][4];
#pragma unroll
            for (int mt = 0; mt < 2; mt++){
                int row = m0 + mt*16 + (lid & 15);
                int col = t0 + ((lid >> 4) << 3);
                uint32_t ao = (uint32_t)(row*P_ST + col)*2u;
                ldmx4(aH[mt][0], aH[mt][1], aH[mt][2], aH[mt][3], sb + SM_PHI + ao);
                ldmx4(aL[mt][0], aL[mt][1], aL[mt][2], aL[mt][3], sb + SM_PLO + ao);
            }
#pragma unroll
            for (int dtp = 0; dtp < 2; dtp++){
                int row = t0 + (lid & 7) + (((lid >> 3) & 1) << 3);
                int col = n2 + dtp*16 + ((lid >> 4) << 3);
                uint32_t bo = (uint32_t)(row*QK_ST + col)*2u;
                uint32_t h0, h1, h2, h3, l0, l1, l2, l3;
                ldmx4t(h0, h1, h2, h3, sb + SM_VHI + bo);
                ldmx4t(l0, l1, l2, l3, sb + SM_VLO + bo);
#pragma unroll
                for (int mt = 0; mt < 2; mt++){
                    mma16816(acc2[mt][2*dtp],   aH[mt], h0, h1);
                    mma16816(acc2[mt][2*dtp+1], aH[mt], h2, h3);
                    mma16816(acc2[mt][2*dtp],   aH[mt], l0, l1);
                    mma16816(acc2[mt][2*dtp+1], aH[mt], l2, l3);
                    mma16816(acc2[mt][2*dtp],   aL[mt], h0, h1);
                    mma16816(acc2[mt][2*dtp+1], aL[mt], h2, h3);
                }
            }
        }
    }

    // ---- context epilogue: [s, b, h*64+d] ----
#pragma unroll
    for (int mt = 0; mt < 2; mt++){
        int rlo = m0 + mt*16 + (lid >> 2);
        float* o0 = out + (size_t)(s0 + rlo)*(BB*HID) + (size_t)b*HID + h*DH;
        float* o1 = o0 + (size_t)8*(BB*HID);
#pragma unroll
        for (int nt = 0; nt < 4; nt++){
            int col = n2 + nt*8 + 2*(lid & 3);
            *reinterpret_cast<float2*>(o0 + col) = make_float2(acc2[mt][nt][0], acc2[mt][nt][1]);
            *reinterpret_cast<float2*>(o1 + col) = make_float2(acc2[mt][nt][2], acc2[mt][nt][3]);
        }
    }
}

// ---------------------------------------------------------------------------
extern "C" void kernel_launch(void* const* d_in, const int* in_sizes, int n_in,
                              void* d_out, int out_size)
{
    const float* x   = (const float*)d_in[0];
    const float* wqa = (const float*)d_in[1];
    const float* bqa = (const float*)d_in[2];
    const float* wqb = (const float*)d_in[3];
    const float* bqb = (const float*)d_in[4];
    const float* wka = (const float*)d_in[5];
    const float* bka = (const float*)d_in[6];
    const float* wkb = (const float*)d_in[7];
    const float* bkb = (const float*)d_in[8];
    const float* wva = (const float*)d_in[9];
    const float* bva = (const float*)d_in[10];
    const float* wvb = (const float*)d_in[11];
    const float* bvb = (const float*)d_in[12];
    float* out = (float*)d_out;

    cudaFuncSetAttribute(k_attn, cudaFuncAttributeMaxDynamicSharedMemorySize, SM_TOTAL);

    k_proja<<<dim3(64, 4), 256>>>(x, wqa, bqa, wka, bka, wva, bva);
    k_projb<<<dim3(64, 16, 3), 256>>>(wqb, bqb, wkb, bkb, wvb, bvb);
    k_attn<<<dim3(16, 32), 256, SM_TOTAL>>>(out);
}

// round 12
// speedup vs baseline: 3.7219x; 1.0716x over previous
#include <cuda_runtime.h>
#include <cuda_bf16.h>
#include <cstdint>

#define SQ   2048
#define BB   2
#define HID  1024
#define NH   16
#define DH   64
#define RK   64
#define NT   (SQ*BB)
#define BHN  (BB*NH)
#define CTXE ((size_t)SQ*BB*HID)

// ---------------- device scratch (no allocation allowed) ----------------
__device__ float g_sq[2][BHN*SQ];          // ||q||^2, ||k||^2
__device__ __nv_bfloat16 g_xhi[NT*HID], g_xlo[NT*HID];          // split x
__device__ __nv_bfloat16 g_wat_hi[3*RK*HID], g_wat_lo[3*RK*HID]; // wa^T [n][k]
__device__ __nv_bfloat16 g_wbt_hi[3*HID*RK], g_wbt_lo[3*HID*RK]; // wb^T [n][k]
__device__ __nv_bfloat16 g_thi[3*NT*RK], g_tlo[3*NT*RK];         // A-stage out
__device__ __nv_bfloat16 g_qhi[BHN*SQ*DH], g_qlo[BHN*SQ*DH];
__device__ __nv_bfloat16 g_khi[BHN*SQ*DH], g_klo[BHN*SQ*DH];
__device__ __nv_bfloat16 g_vhi[BHN*SQ*DH], g_vlo[BHN*SQ*DH];

__device__ __forceinline__ uint32_t s2u(const void* p){
    uint32_t a;
    asm("{ .reg .u64 t; cvta.to.shared.u64 t, %1; cvt.u32.u64 %0, t; }" : "=r"(a) : "l"(p));
    return a;
}

// ---------------- mma.sync helpers (baseline ISA) ------
__device__ __forceinline__ void ldmx4(uint32_t& r0, uint32_t& r1, uint32_t& r2, uint32_t& r3,
                                      uint32_t addr){
    asm volatile("ldmatrix.sync.aligned.m8n8.x4.shared.b16 {%0,%1,%2,%3}, [%4];"
        : "=r"(r0), "=r"(r1), "=r"(r2), "=r"(r3) : "r"(addr));
}
__device__ __forceinline__ void ldmx4t(uint32_t& r0, uint32_t& r1, uint32_t& r2, uint32_t& r3,
                                       uint32_t addr){
    asm volatile("ldmatrix.sync.aligned.m8n8.x4.trans.shared.b16 {%0,%1,%2,%3}, [%4];"
        : "=r"(r0), "=r"(r1), "=r"(r2), "=r"(r3) : "r"(addr));
}
__device__ __forceinline__ void mma16816(float* d, const uint32_t* a, uint32_t b0, uint32_t b1){
    asm volatile("mma.sync.aligned.m16n8k16.row.col.f32.bf16.bf16.f32 "
        "{%0,%1,%2,%3},{%4,%5,%6,%7},{%8,%9},{%0,%1,%2,%3};"
        : "+f"(d[0]), "+f"(d[1]), "+f"(d[2]), "+f"(d[3])
        : "r"(a[0]), "r"(a[1]), "r"(a[2]), "r"(a[3]), "r"(b0), "r"(b1));
}
// Packed bf16 hi/lo split.
__device__ __forceinline__ void split2(float x, float y, uint32_t& hi, uint32_t& lo){
    uint32_t h;
    asm("cvt.rn.bf16x2.f32 %0, %1, %2;" : "=r"(h) : "f"(y), "f"(x));
    float xh = __uint_as_float(h << 16);
    float yh = __uint_as_float(h & 0xFFFF0000u);
    float xl = x - xh, yl = y - yh;
    uint32_t l;
    asm("cvt.rn.bf16x2.f32 %0, %1, %2;" : "=r"(l) : "f"(yl), "f"(xl));
    hi = h; lo = l;
}
__device__ __forceinline__ void cpa16(uint32_t dst, const void* src){
    asm volatile("cp.async.cg.shared.global [%0], [%1], 16;" :: "r"(dst), "l"(src));
}
#define CP_COMMIT() asm volatile("cp.async.commit_group;")
#define CP_WAIT(n)  asm volatile("cp.async.wait_group %0;" :: "n"(n))

// ---------------------------------------------------------------------------
// Kernel 0a: split x -> bf16 hi/lo.  grid 2048 x 256, 8 elems/thread.
// ---------------------------------------------------------------------------
__global__ void __launch_bounds__(256) k_splitx(const float* __restrict__ x)
{
    size_t base = ((size_t)blockIdx.x*256 + threadIdx.x)*8;
    float4 a = *reinterpret_cast<const float4*>(x + base);
    float4 b = *reinterpret_cast<const float4*>(x + base + 4);
    uint32_t h0,l0,h1,l1,h2,l2,h3,l3;
    split2(a.x, a.y, h0, l0); split2(a.z, a.w, h1, l1);
    split2(b.x, b.y, h2, l2); split2(b.z, b.w, h3, l3);
    *reinterpret_cast<uint4*>(g_xhi + base) = make_uint4(h0,h1,h2,h3);
    *reinterpret_cast<uint4*>(g_xlo + base) = make_uint4(l0,l1,l2,l3);
}

// ---------------------------------------------------------------------------
// Kernel 0b: transpose+split weights.  by=0: wa[1024,64]->wat[64][1024];
// by=1: wb[64,1024]->wbt[1024][64].  grid (16, 2, 3).
// ---------------------------------------------------------------------------
__global__ void __launch_bounds__(256) k_splitw(
    const float* __restrict__ wqa, const float* __restrict__ wka, const float* __restrict__ wva,
    const float* __restrict__ wqb, const float* __restrict__ wkb, const float* __restrict__ wvb)
{
    const int mat = blockIdx.z;
    if (blockIdx.y == 0){
        const float* wa = (mat==0) ? wqa : (mat==1 ? wka : wva);
#pragma unroll
        for (int it = 0; it < 8; it++){
            int o2 = (blockIdx.x*2048 + it*256 + threadIdx.x)*2;
            int n = o2 >> 10, k = o2 & 1023;
            float v0 = wa[(size_t)k*RK + n];
            float v1 = wa[(size_t)(k+1)*RK + n];
            uint32_t h, l; split2(v0, v1, h, l);
            *reinterpret_cast<uint32_t*>(g_wat_hi + (size_t)mat*RK*HID + o2) = h;
            *reinterpret_cast<uint32_t*>(g_wat_lo + (size_t)mat*RK*HID + o2) = l;
        }
    } else {
        const float* wb = (mat==0) ? wqb : (mat==1 ? wkb : wvb);
#pragma unroll
        for (int it = 0; it < 8; it++){
            int o2 = (blockIdx.x*2048 + it*256 + threadIdx.x)*2;
            int n = o2 >> 6, k = o2 & 63;
            float v0 = wb[(size_t)k*HID + n];
            float v1 = wb[(size_t)(k+1)*HID + n];
            uint32_t h, l; split2(v0, v1, h, l);
            *reinterpret_cast<uint32_t*>(g_wbt_hi + (size_t)mat*HID*RK + o2) = h;
            *reinterpret_cast<uint32_t*>(g_wbt_lo + (size_t)mat*HID*RK + o2) = l;
        }
    }
}

// ---------------------------------------------------------------------------
// Kernel 1: A-stage via HMMA.  t[m][n] = sum_k x[m][k] wat[n][k]  (+ba), bf16x3.
// grid (128 Mtiles of 32, 3 mats), 256 threads.  warps: 2M(16) x 4N(16).
// ---------------------------------------------------------------------------
__global__ void __launch_bounds__(256) k_proja(
    const float* __restrict__ b0, const float* __restrict__ b1, const float* __restrict__ b2)
{
    __shared__ __align__(16) __nv_bfloat16 XH[32*72], XL[32*72];
    __shared__ __align__(16) __nv_bfloat16 WH[64*72], WL[64*72];
    const int mat = blockIdx.y, m0 = blockIdx.x*32;
    const int tid = threadIdx.x, lid = tid & 31, wid = tid >> 5;
    const int mw = wid & 1, nw = wid >> 1;
    const uint32_t xh = s2u(XH), xl = s2u(XL), wh = s2u(WH), wl = s2u(WL);
    const __nv_bfloat16* wat_h = g_wat_hi + (size_t)mat*RK*HID;
    const __nv_bfloat16* wat_l = g_wat_lo + (size_t)mat*RK*HID;

    float acc[2][4];
#pragma unroll
    for (int nt = 0; nt < 2; nt++)
#pragma unroll
        for (int q = 0; q < 4; q++) acc[nt][q] = 0.0f;

    for (int kc = 0; kc < 16; kc++){
        __syncthreads();
        {
            int r = tid >> 3, c8 = (tid & 7)*8;
            *reinterpret_cast<uint4*>(XH + r*72 + c8) =
                *reinterpret_cast<const uint4*>(g_xhi + (size_t)(m0+r)*HID + kc*64 + c8);
            *reinterpret_cast<uint4*>(XL + r*72 + c8) =
                *reinterpret_cast<const uint4*>(g_xlo + (size_t)(m0+r)*HID + kc*64 + c8);
#pragma unroll
            for (int it = 0; it < 2; it++){
                int e = tid + it*256;
                int wr = e >> 3, wc8 = (e & 7)*8;
                *reinterpret_cast<uint4*>(WH + wr*72 + wc8) =
                    *reinterpret_cast<const uint4*>(wat_h + (size_t)wr*HID + kc*64 + wc8);
                *reinterpret_cast<uint4*>(WL + wr*72 + wc8) =
                    *reinterpret_cast<const uint4*>(wat_l + (size_t)wr*HID + kc*64 + wc8);
            }
        }
        __syncthreads();
#pragma unroll
        for (int ks = 0; ks < 4; ks++){
            const int d0 = ks*16;
            int arow = mw*16 + (lid & 15);
            int acol = d0 + ((lid >> 4) << 3);
            uint32_t aH[4], aL[4];
            ldmx4(aH[0], aH[1], aH[2], aH[3], xh + (uint32_t)(arow*72 + acol)*2u);
            ldmx4(aL[0], aL[1], aL[2], aL[3], xl + (uint32_t)(arow*72 + acol)*2u);
            int brow = nw*16 + (lid & 7) + ((lid >> 4) << 3);
            int bcol = d0 + (((lid >> 3) & 1) << 3);
            uint32_t bh0, bh1, bh2, bh3, bl0, bl1, bl2, bl3;
            ldmx4(bh0, bh1, bh2, bh3, wh + (uint32_t)(brow*72 + bcol)*2u);
            ldmx4(bl0, bl1, bl2, bl3, wl + (uint32_t)(brow*72 + bcol)*2u);
            mma16816(acc[0], aH, bh0, bh1); mma16816(acc[1], aH, bh2, bh3);
            mma16816(acc[0], aH, bl0, bl1); mma16816(acc[1], aH, bl2, bl3);
            mma16816(acc[0], aL, bh0, bh1); mma16816(acc[1], aL, bh2, bh3);
        }
    }

    const float* ba = (mat==0) ? b0 : (mat==1 ? b1 : b2);
    __nv_bfloat16* th = g_thi + (size_t)mat*NT*RK;
    __nv_bfloat16* tl = g_tlo + (size_t)mat*NT*RK;
    int rlo = mw*16 + (lid >> 2);
#pragma unroll
    for (int nt = 0; nt < 2; nt++){
        int c0 = nw*16 + nt*8 + 2*(lid & 3);
        float ba0 = ba[c0], ba1 = ba[c0+1];
        uint32_t hw, lw;
        split2(acc[nt][0] + ba0, acc[nt][1] + ba1, hw, lw);
        *reinterpret_cast<uint32_t*>(th + (size_t)(m0+rlo)*RK + c0) = hw;
        *reinterpret_cast<uint32_t*>(tl + (size_t)(m0+rlo)*RK + c0) = lw;
        split2(acc[nt][2] + ba0, acc[nt][3] + ba1, hw, lw);
        *reinterpret_cast<uint32_t*>(th + (size_t)(m0+rlo+8)*RK + c0) = hw;
        *reinterpret_cast<uint32_t*>(tl + (size_t)(m0+rlo+8)*RK + c0) = lw;
    }
}

// ---------------------------------------------------------------------------
// Kernel 2: B-stage via HMMA.  q/k/v = t @ wb (+bb), bf16x3; emits hi/lo + sq.
// grid (64 Mtiles of 64, 16 heads, 3 mats), 256 threads. warps: 2M(32) x 4N(16).
// ---------------------------------------------------------------------------
__global__ void __launch_bounds__(256) k_projb(
    const float* __restrict__ b0, const float* __restrict__ b1, const float* __restrict__ b2)
{
    __shared__ __align__(16) __nv_bfloat16 TH[64*72], TL[64*72];
    __shared__ __align__(16) __nv_bfloat16 WH[64*72], WL[64*72];
    __shared__ float sqp[64*4];
    const int mat = blockIdx.z, h = blockIdx.y, m0 = blockIdx.x*64;
    const int tid = threadIdx.x, lid = tid & 31, wid = tid >> 5;
    const int mw = wid & 1, nw = wid >> 1;
    const uint32_t thp = s2u(TH), tlp = s2u(TL), whp = s2u(WH), wlp = s2u(WL);

#pragma unroll
    for (int it = 0; it < 2; it++){
        int e = tid + it*256;
        int r = e >> 3, c8 = (e & 7)*8;
        *reinterpret_cast<uint4*>(TH + r*72 + c8) =
            *reinterpret_cast<const uint4*>(g_thi + (size_t)mat*NT*RK + (size_t)(m0+r)*RK + c8);
        *reinterpret_cast<uint4*>(TL + r*72 + c8) =
            *reinterpret_cast<const uint4*>(g_tlo + (size_t)mat*NT*RK + (size_t)(m0+r)*RK + c8);
        *reinterpret_cast<uint4*>(WH + r*72 + c8) =
            *reinterpret_cast<const uint4*>(g_wbt_hi + ((size_t)mat*HID + h*64 + r)*RK + c8);
        *reinterpret_cast<uint4*>(WL + r*72 + c8) =
            *reinterpret_cast<const uint4*>(g_wbt_lo + ((size_t)mat*HID + h*64 + r)*RK + c8);
    }
    __syncthreads();

    float acc[2][2][4];
#pragma unroll
    for (int mt = 0; mt < 2; mt++)
#pragma unroll
        for (int nt = 0; nt < 2; nt++)
#pragma unroll
            for (int q = 0; q < 4; q++) acc[mt][nt][q] = 0.0f;

#pragma unroll
    for (int ks = 0; ks < 4; ks++){
        const int d0 = ks*16;
        uint32_t aH[2][4], aL[2][4];
#pragma unroll
        for (int mt = 0; mt < 2; mt++){
            int arow = mw*32 + mt*16 + (lid & 15);
            int acol = d0 + ((lid >> 4) << 3);
            ldmx4(aH[mt][0], aH[mt][1], aH[mt][2], aH[mt][3], thp + (uint32_t)(arow*72 + acol)*2u);
            ldmx4(aL[mt][0], aL[mt][1], aL[mt][2], aL[mt][3], tlp + (uint32_t)(arow*72 + acol)*2u);
        }
        int brow = nw*16 + (lid & 7) + ((lid >> 4) << 3);
        int bcol = d0 + (((lid >> 3) & 1) << 3);
        uint32_t bh0, bh1, bh2, bh3, bl0, bl1, bl2, bl3;
        ldmx4(bh0, bh1, bh2, bh3, whp + (uint32_t)(brow*72 + bcol)*2u);
        ldmx4(bl0, bl1, bl2, bl3, wlp + (uint32_t)(brow*72 + bcol)*2u);
#pragma unroll
        for (int mt = 0; mt < 2; mt++){
            mma16816(acc[mt][0], aH[mt], bh0, bh1); mma16816(acc[mt][1], aH[mt], bh2, bh3);
            mma16816(acc[mt][0], aH[mt], bl0, bl1); mma16816(acc[mt][1], aH[mt], bl2, bl3);
            mma16816(acc[mt][0], aL[mt], bh0, bh1); mma16816(acc[mt][1], aL[mt], bh2, bh3);
        }
    }

    const float* bb = (mat==0) ? b0 : (mat==1 ? b1 : b2);
    __nv_bfloat16* ph = (mat==0) ? g_qhi : (mat==1 ? g_khi : g_vhi);
    __nv_bfloat16* pl = (mat==0) ? g_qlo : (mat==1 ? g_klo : g_vlo);
    float sqa[4] = {0.f, 0.f, 0.f, 0.f};
#pragma unroll
    for (int mt = 0; mt < 2; mt++){
        int rl = mw*32 + mt*16 + (lid >> 2);
#pragma unroll
        for (int nt = 0; nt < 2; nt++){
            int c0 = nw*16 + nt*8 + 2*(lid & 3);
            float bb0 = bb[h*64 + c0], bb1 = bb[h*64 + c0 + 1];
            float v00 = acc[mt][nt][0] + bb0, v01 = acc[mt][nt][1] + bb1;
            float v10 = acc[mt][nt][2] + bb0, v11 = acc[mt][nt][3] + bb1;
            int m1 = m0 + rl;
            int s1 = m1 >> 1, bh1i = (m1 & 1)*NH + h;
            uint32_t hw, lw;
            split2(v00, v01, hw, lw);
            *reinterpret_cast<uint32_t*>(ph + ((size_t)bh1i*SQ + s1)*DH + c0) = hw;
            *reinterpret_cast<uint32_t*>(pl + ((size_t)bh1i*SQ + s1)*DH + c0) = lw;
            int m2 = m1 + 8;
            int s2 = m2 >> 1, bh2i = (m2 & 1)*NH + h;
            split2(v10, v11, hw, lw);
            *reinterpret_cast<uint32_t*>(ph + ((size_t)bh2i*SQ + s2)*DH + c0) = hw;
            *reinterpret_cast<uint32_t*>(pl + ((size_t)bh2i*SQ + s2)*DH + c0) = lw;
            sqa[mt*2+0] += v00*v00 + v01*v01;
            sqa[mt*2+1] += v10*v10 + v11*v11;
        }
    }
#pragma unroll
    for (int i = 0; i < 4; i++){
        sqa[i] += __shfl_xor_sync(0xffffffffu, sqa[i], 1);
        sqa[i] += __shfl_xor_sync(0xffffffffu, sqa[i], 2);
    }
    if ((lid & 3) == 0){
#pragma unroll
        for (int mt = 0; mt < 2; mt++){
            int rl = mw*32 + mt*16 + (lid >> 2);
            sqp[rl*4 + nw]     = sqa[mt*2+0];
            sqp[(rl+8)*4 + nw] = sqa[mt*2+1];
        }
    }
    __syncthreads();
    if (mat < 2 && tid < 64){
        float s4 = sqp[tid*4] + sqp[tid*4+1] + sqp[tid*4+2] + sqp[tid*4+3];
        int m = m0 + tid;
        int s = m >> 1, bh = (m & 1)*NH + h;
        g_sq[mat][(size_t)bh*SQ + s] = s4;
    }
}

// ---------------------------------------------------------------------------
// Kernel 3: mma.sync bf16x3 attention (unchanged from R11).
// ---------------------------------------------------------------------------
#define QK_ST 72
#define P_ST  72
#define SM_QSQ 0
#define SM_KSQ 512
#define SM_QHI 1024
#define SM_QLO (SM_QHI + 18432)
#define SM_KHI (SM_QLO + 18432)
#define SM_KLO (SM_KHI + 9216)
#define SM_VHI (SM_KLO + 9216)
#define SM_VLO (SM_VHI + 9216)
#define SM_PHI (SM_VLO + 9216)
#define SM_PLO (SM_PHI + 18432)
#define SM_TOTAL (SM_PLO + 18432)   // 111616 bytes

__global__ void __launch_bounds__(256, 2) k_attn(float* __restrict__ out)
{
    extern __shared__ __align__(16) char sm[];
    const uint32_t sb = s2u(sm);
    const int tid = threadIdx.x, lid = tid & 31, wid = tid >> 5;
    const int bh = blockIdx.y, b = bh >> 4, h = bh & 15;
    const int s0 = blockIdx.x * 128;

    const size_t kvbase = (size_t)bh*SQ*DH;
    const int lr  = tid >> 3;
    const int lc8 = (tid & 7) * 8;
    const uint32_t lso = (uint32_t)(lr*QK_ST + lc8)*2u;

    // prologue: issue K(0)+ksq(0)
    {
#pragma unroll
        for (int it = 0; it < 2; it++){
            uint32_t so = lso + (uint32_t)(it*32*QK_ST)*2u;
            size_t go = kvbase + (size_t)(lr + it*32)*DH + lc8;
            cpa16(sb + SM_KHI + so, g_khi + go);
            cpa16(sb + SM_KLO + so, g_klo + go);
        }
        if (tid < 16)
            cpa16(sb + SM_KSQ + (uint32_t)tid*16u, g_sq[1] + (size_t)bh*SQ + tid*4);
        CP_COMMIT();
    }

    // resident Q tiles (hi/lo) + qsq
    {
        const __nv_bfloat16* qh = g_qhi + ((size_t)bh*SQ + s0)*DH;
        const __nv_bfloat16* ql = g_qlo + ((size_t)bh*SQ + s0)*DH;
#pragma unroll
        for (int it = 0; it < 4; it++){
            int e = tid + it*256;
            int r = e >> 3, c8 = (e & 7)*8;
            uint32_t so = (uint32_t)(r*QK_ST + c8)*2u;
            *reinterpret_cast<uint4*>(sm + SM_QHI + so) =
                *reinterpret_cast<const uint4*>(qh + (size_t)r*DH + c8);
            *reinterpret_cast<uint4*>(sm + SM_QLO + so) =
                *reinterpret_cast<const uint4*>(ql + (size_t)r*DH + c8);
        }
        if (tid < 128)
            reinterpret_cast<float*>(sm + SM_QSQ)[tid] = g_sq[0][(size_t)bh*SQ + s0 + tid];
    }

    const int m0 = (wid & 3) * 32;
    const int n1 = (wid >> 2) * 32;
    const int n2 = (wid >> 2) * 32;

    float acc2[2][4][4];
#pragma unroll
    for (int mt = 0; mt < 2; mt++)
#pragma unroll
        for (int nt = 0; nt < 4; nt++)
#pragma unroll
            for (int q = 0; q < 4; q++) acc2[mt][nt][q] = 0.0f;

    for (int kt = 0; kt < 32; kt++){
        __syncthreads();
        {
            const size_t off = kvbase + (size_t)kt*64*DH;
#pragma unroll
            for (int it = 0; it < 2; it++){
                uint32_t so = lso + (uint32_t)(it*32*QK_ST)*2u;
                size_t go = off + (size_t)(lr + it*32)*DH + lc8;
                cpa16(sb + SM_VHI + so, g_vhi + go);
                cpa16(sb + SM_VLO + so, g_vlo + go);
            }
            CP_COMMIT();
        }
        CP_WAIT(1);
        __syncthreads();

        // GEMM1
        float acc1[2][4][4];
#pragma unroll
        for (int mt = 0; mt < 2; mt++)
#pragma unroll
            for (int nt = 0; nt < 4; nt++)
#pragma unroll
                for (int q = 0; q < 4; q++) acc1[mt][nt][q] = 0.0f;

#pragma unroll
        for (int ks = 0; ks < 4; ks++){
            const int d0 = ks*16;
            uint32_t aH[2][4], aL[2][4];
#pragma unroll
            for (int mt = 0; mt < 2; mt++){
                int row = m0 + mt*16 + (lid & 15);
                int col = d0 + ((lid >> 4) << 3);
                uint32_t ao = (uint32_t)(row*QK_ST + col)*2u;
                ldmx4(aH[mt][0], aH[mt][1], aH[mt][2], aH[mt][3], sb + SM_QHI + ao);
                ldmx4(aL[mt][0], aL[mt][1], aL[mt][2], aL[mt][3], sb + SM_QLO + ao);
            }
#pragma unroll
            for (int ntp = 0; ntp < 2; ntp++){
                int row = n1 + ntp*16 + (lid & 7) + ((lid >> 4) << 3);
                int col = d0 + (((lid >> 3) & 1) << 3);
                uint32_t bo = (uint32_t)(row*QK_ST + col)*2u;
                uint32_t h0, h1, h2, h3, l0, l1, l2, l3;
                ldmx4(h0, h1, h2, h3, sb + SM_KHI + bo);
                ldmx4(l0, l1, l2, l3, sb + SM_KLO + bo);
#pragma unroll
                for (int mt = 0; mt < 2; mt++){
                    mma16816(acc1[mt][2*ntp],   aH[mt], h0, h1);
                    mma16816(acc1[mt][2*ntp+1], aH[mt], h2, h3);
                    mma16816(acc1[mt][2*ntp],   aH[mt], l0, l1);
                    mma16816(acc1[mt][2*ntp+1], aH[mt], l2, l3);
                    mma16816(acc1[mt][2*ntp],   aL[mt], h0, h1);
                    mma16816(acc1[mt][2*ntp+1], aL[mt], h2, h3);
                }
            }
        }

        // epilogue
        {
            const float* qsq = reinterpret_cast<const float*>(sm + SM_QSQ);
            const float* ksq = reinterpret_cast<const float*>(sm + SM_KSQ);
#pragma unroll
            for (int mt = 0; mt < 2; mt++){
                int rlo = m0 + mt*16 + (lid >> 2);
                float q0 = qsq[rlo], q1 = qsq[rlo + 8];
                float* sr0 = out + CTXE + ((size_t)bh*SQ + (size_t)(s0 + rlo))*SQ + kt*64;
                float* sr1 = sr0 + (size_t)8*SQ;
#pragma unroll
                for (int nt = 0; nt < 4; nt++){
                    int col = n1 + nt*8 + 2*(lid & 3);
                    float k0 = ksq[col], k1 = ksq[col+1];
                    float s00 = fmaf(0.125f, acc1[mt][nt][0], -0.0625f*(q0 + k0));
                    float s01 = fmaf(0.125f, acc1[mt][nt][1], -0.0625f*(q0 + k1));
                    float s10 = fmaf(0.125f, acc1[mt][nt][2], -0.0625f*(q1 + k0));
                    float s11 = fmaf(0.125f, acc1[mt][nt][3], -0.0625f*(q1 + k1));
                    *reinterpret_cast<float2*>(sr0 + col) = make_float2(s00, s01);
                    *reinterpret_cast<float2*>(sr1 + col) = make_float2(s10, s11);
                    uint32_t hw, lw;
                    split2(__expf(s00), __expf(s01), hw, lw);
                    *reinterpret_cast<uint32_t*>(sm + SM_PHI + (uint32_t)(rlo*P_ST + col)*2u) = hw;
                    *reinterpret_cast<uint32_t*>(sm + SM_PLO + (uint32_t)(rlo*P_ST + col)*2u) = lw;
                    split2(__expf(s10), __expf(s11), hw, lw);
                    *reinterpret_cast<uint32_t*>(sm + SM_PHI + (uint32_t)((rlo+8)*P_ST + col)*2u) = hw;
                    *reinterpret_cast<uint32_t*>(sm + SM_PLO + (uint32_t)((rlo+8)*P_ST + col)*2u) = lw;
                }
            }
        }
        CP_WAIT(0);
        __syncthreads();

        // prefetch K(kt+1)
        if (kt + 1 < 32){
            const size_t off = kvbase + (size_t)(kt+1)*64*DH;
#pragma unroll
            for (int it = 0; it < 2; it++){
                uint32_t so = lso + (uint32_t)(it*32*QK_ST)*2u;
                size_t go = off + (size_t)(lr + it*32)*DH + lc8;
                cpa16(sb + SM_KHI + so, g_khi + go);
                cpa16(sb + SM_KLO + so, g_klo + go);
            }
            if (tid < 16)
                cpa16(sb + SM_KSQ + (uint32_t)tid*16u,
                      g_sq[1] + (size_t)bh*SQ + (kt+1)*64 + tid*4);
            CP_COMMIT();
        } else {
            CP_COMMIT();
        }

        // GEMM2
#pragma unroll
        for (int ks = 0; ks < 4; ks++){
            const int t0 = ks*16;
            uint32_t aH[2][4], aL[2][4];
#pragma unroll
            for (int mt = 0; mt < 2; mt++){
                int row = m0 + mt*16 + (lid & 15);
                int col = t0 + ((lid >> 4) << 3);
                uint32_t ao = (uint32_t)(row*P_ST + col)*2u;
                ldmx4(aH[mt][0], aH[mt][1], aH[mt][2], aH[mt][3], sb + SM_PHI + ao);
                ldmx4(aL[mt][0], aL[mt][1], aL[mt][2], aL[mt][3], sb + SM_PLO + ao);
            }
#pragma unroll
            for (int dtp = 0; dtp < 2; dtp++){
                int row = t0 + (lid & 7) + (((lid >> 3) & 1) << 3);
                int col = n2 + dtp*16 + ((lid >> 4) << 3);
                uint32_t bo = (uint32_t)(row*QK_ST + col)*2u;
                uint32_t h0, h1, h2, h3, l0, l1, l2, l3;
                ldmx4t(h0, h1, h2, h3, sb + SM_VHI + bo);
                ldmx4t(l0, l1, l2, l3, sb + SM_VLO + bo);
#pragma unroll
                for (int mt = 0; mt < 2; mt++){
                    mma16816(acc2[mt][2*dtp],   aH[mt], h0, h1);
                    mma16816(acc2[mt][2*dtp+1], aH[mt], h2, h3);
                    mma16816(acc2[mt][2*dtp],   aH[mt], l0, l1);
                    mma16816(acc2[mt][2*dtp+1], aH[mt], l2, l3);
                    mma16816(acc2[mt][2*dtp],   aL[mt], h0, h1);
                    mma16816(acc2[mt][2*dtp+1], aL[mt], h2, h3);
                }
            }
        }
    }

    // context epilogue
#pragma unroll
    for (int mt = 0; mt < 2; mt++){
        int rlo = m0 + mt*16 + (lid >> 2);
        float* o0 = out + (size_t)(s0 + rlo)*(BB*HID) + (size_t)b*HID + h*DH;
        float* o1 = o0 + (size_t)8*(BB*HID);
#pragma unroll
        for (int nt = 0; nt < 4; nt++){
            int col = n2 + nt*8 + 2*(lid & 3);
            *reinterpret_cast<float2*>(o0 + col) = make_float2(acc2[mt][nt][0], acc2[mt][nt][1]);
            *reinterpret_cast<float2*>(o1 + col) = make_float2(acc2[mt][nt][2], acc2[mt][nt][3]);
        }
    }
}

// ---------------------------------------------------------------------------
extern "C" void kernel_launch(void* const* d_in, const int* in_sizes, int n_in,
                              void* d_out, int out_size)
{
    const float* x   = (const float*)d_in[0];
    const float* wqa = (const float*)d_in[1];
    const float* bqa = (const float*)d_in[2];
    const float* wqb = (const float*)d_in[3];
    const float* bqb = (const float*)d_in[4];
    const float* wka = (const float*)d_in[5];
    const float* bka = (const float*)d_in[6];
    const float* wkb = (const float*)d_in[7];
    const float* bkb = (const float*)d_in[8];
    const float* wva = (const float*)d_in[9];
    const float* bva = (const float*)d_in[10];
    const float* wvb = (const float*)d_in[11];
    const float* bvb = (const float*)d_in[12];
    float* out = (float*)d_out;

    cudaFuncSetAttribute(k_attn, cudaFuncAttributeMaxDynamicSharedMemorySize, SM_TOTAL);

    k_splitx<<<2048, 256>>>(x);
    k_splitw<<<dim3(16, 2, 3), 256>>>(wqa, wka, wva, wqb, wkb, wvb);
    k_proja<<<dim3(128, 3), 256>>>(bqa, bka, bva);
    k_projb<<<dim3(64, 16, 3), 256>>>(bqb, bkb, bvb);
    k_attn<<<dim3(16, 32), 256, SM_TOTAL>>>(out);
}